// round 13
// baseline (speedup 1.0000x reference)
#include <cuda_runtime.h>
#include <cuda_fp16.h>
#include <math.h>
#include <stdint.h>

#define N_NODES 100000
#define N_EDGES 1600000
#define HID 128
#define EPS 1e-5f
#define N_TILES 782          // ceil(100000/128)
#define SM_STRIDE 136        // floats per staged row; 136 % 32 == 8 -> conflict-free frag LDS
#define SMEM_MMA (8 * 16 * SM_STRIDE * 4)   // 69632 B

// ---------------- scratch (device globals; referenced ONLY in device code) ----------------
__device__ float  d_h0[N_NODES * HID];
__device__ float  d_h1[N_NODES * HID];
__device__ __half d_g [N_NODES * HID];   // fp16 gather table: dinv-scaled h@W ; head reuses bytes as ff[N,32] fp32
__device__ float  d_agg[N_NODES * HID];  // fp32 aggregate stream (fp16 here compounds error across layers -> fails gate)
__device__ float  d_dinv[N_NODES];
__device__ int    d_cnt[N_NODES];
__device__ int    d_cursor[N_NODES];
__device__ int    d_rowptr[N_NODES + 1];
__device__ int    d_col[N_EDGES];
__device__ int    d_bsums[128];
__device__ double d_bnSum[HID];
__device__ double d_bnSqs[HID];
__device__ float  d_bnA[HID];
__device__ float  d_bnC[HID];
// B-fragment images: per (layer, kt, nt, lane): uint4 {bhi0, bhi1, blo0, blo1}
__device__ uint4  d_Wfrag[3 * 128 * 32];

// ---------------- helpers ----------------
__device__ __forceinline__ float* hbuf(int sel) { return sel == 0 ? d_h0 : d_h1; }

__device__ __forceinline__ uint32_t pack_bf16x2(float lo, float hi) {
    uint32_t d;
    asm("cvt.rn.bf16x2.f32 %0, %2, %1;" : "=r"(d) : "f"(lo), "f"(hi));
    return d;
}
__device__ __forceinline__ float bf_lo(uint32_t v) { return __uint_as_float(v << 16); }
__device__ __forceinline__ float bf_hi(uint32_t v) { return __uint_as_float(v & 0xffff0000u); }

// split float2 -> bf16x2 hi image + bf16x2 residual image
__device__ __forceinline__ void split2(float a, float b, uint32_t& hi, uint32_t& lo) {
    hi = pack_bf16x2(a, b);
    lo = pack_bf16x2(a - bf_lo(hi), b - bf_hi(hi));
}

__device__ __forceinline__ void mma_bf16(float c[4], uint32_t a0, uint32_t a1,
                                         uint32_t a2, uint32_t a3,
                                         uint32_t b0, uint32_t b1) {
    asm volatile(
        "mma.sync.aligned.m16n8k16.row.col.f32.bf16.bf16.f32 "
        "{%0,%1,%2,%3}, {%4,%5,%6,%7}, {%8,%9}, {%0,%1,%2,%3};"
        : "+f"(c[0]), "+f"(c[1]), "+f"(c[2]), "+f"(c[3])
        : "r"(a0), "r"(a1), "r"(a2), "r"(a3), "r"(b0), "r"(b1));
}

// accumulate 4 halves (as uint2) into float4
__device__ __forceinline__ void addh4(float4& a, uint2 v) {
    float2 f0 = __half22float2(*reinterpret_cast<const __half2*>(&v.x));
    float2 f1 = __half22float2(*reinterpret_cast<const __half2*>(&v.y));
    a.x += f0.x; a.y += f0.y; a.z += f1.x; a.w += f1.y;
}

// ---------------- setup kernels ----------------
__global__ void k_zero_counts() {
    int i = blockIdx.x * blockDim.x + threadIdx.x;
    if (i < N_NODES) { d_cnt[i] = 0; d_cursor[i] = 0; }
}
__global__ void k_count(const int* __restrict__ ei) {
    int e = blockIdx.x * blockDim.x + threadIdx.x;
    if (e < N_EDGES) atomicAdd(&d_cnt[ei[N_EDGES + e]], 1);
}
__global__ void k_dinv() {
    int i = blockIdx.x * blockDim.x + threadIdx.x;
    if (i < N_NODES) d_dinv[i] = rsqrtf((float)d_cnt[i] + 1.0f);
}
__global__ void k_scan_local() {
    __shared__ int s[1024];
    int tid = threadIdx.x;
    int idx = blockIdx.x * 1024 + tid;
    int v = (idx < N_NODES) ? d_cnt[idx] : 0;
    s[tid] = v;
    __syncthreads();
    for (int off = 1; off < 1024; off <<= 1) {
        int t = (tid >= off) ? s[tid - off] : 0;
        __syncthreads();
        s[tid] += t;
        __syncthreads();
    }
    if (idx < N_NODES) d_rowptr[idx] = s[tid] - v;   // exclusive
    if (tid == 1023) d_bsums[blockIdx.x] = s[1023];
}
__global__ void k_scan_bsums(int nb) {
    __shared__ int sb[128];
    int t = threadIdx.x;
    sb[t] = (t < nb) ? d_bsums[t] : 0;
    __syncthreads();
    if (t == 0) {
        int run = 0;
        for (int i = 0; i < nb; i++) { int x = sb[i]; sb[i] = run; run += x; }
        d_rowptr[N_NODES] = run;
    }
    __syncthreads();
    if (t < nb) d_bsums[t] = sb[t];
}
__global__ void k_scan_add() {
    int idx = blockIdx.x * 1024 + threadIdx.x;
    if (idx < N_NODES) d_rowptr[idx] += d_bsums[blockIdx.x];
}
__global__ void k_fill(const int* __restrict__ ei) {
    int e = blockIdx.x * blockDim.x + threadIdx.x;
    if (e < N_EDGES) {
        int s = ei[e];
        int d = ei[N_EDGES + e];
        int pos = d_rowptr[d] + atomicAdd(&d_cursor[d], 1);
        d_col[pos] = s;
    }
}

// ---------------- W prep: build per-(kt,nt,lane) B fragments, bf16 hi/lo ----------------
__global__ void k_prep_wfrag(const float* __restrict__ W1,
                             const float* __restrict__ W2,
                             const float* __restrict__ W3) {
    int idx = blockIdx.x * blockDim.x + threadIdx.x;
    if (idx >= 3 * 8 * 16 * 32) return;
    int lane = idx & 31;
    int nt = (idx >> 5) & 15;
    int kt = (idx >> 9) & 7;
    int L  = idx >> 12;
    const float* W = (L == 0) ? W1 : (L == 1) ? W2 : W3;
    int g = lane >> 2, t = lane & 3;
    int n = nt * 8 + g;
    int k0 = kt * 16 + 2 * t;
    int k1 = kt * 16 + 2 * t + 8;
    uint32_t h0, l0, h1, l1;
    split2(W[k0 * 128 + n], W[(k0 + 1) * 128 + n], h0, l0);
    split2(W[k1 * 128 + n], W[(k1 + 1) * 128 + n], h1, l1);
    uint4 v; v.x = h0; v.y = h1; v.z = l0; v.w = l1;
    d_Wfrag[(L * 128 + kt * 16 + nt) * 32 + lane] = v;
}

// ---------------- tensor GEMM: d_g(fp16) = dinv * (h_new @ W_layer) ----------------
__global__ void __launch_bounds__(256, 2) k_mma_gemm(
    const float* __restrict__ x, const float* __restrict__ We,
    const float* __restrict__ be,
    int layer, int hin_sel, int hout_sel, int first) {
    extern __shared__ float smf[];
    const int lane = threadIdx.x & 31;
    const int wid = threadIdx.x >> 5;
    const int tile = blockIdx.x;
    float* sw = smf + wid * 16 * SM_STRIDE;
    const int rbase = tile * 128 + wid * 16;

    if (first && blockIdx.x == 0 && threadIdx.x < HID) {
        d_bnSum[threadIdx.x] = 0.0;
        d_bnSqs[threadIdx.x] = 0.0;
    }

    // ---- phase 1: h_new for this warp's 16 rows ----
    if (first) {
        float4 w0 = __ldg(&((const float4*)We)[lane]);
        float4 w1 = __ldg(&((const float4*)We)[32 + lane]);
        float4 b  = __ldg(&((const float4*)be)[lane]);
        float4* H04 = reinterpret_cast<float4*>(d_h0);
        #pragma unroll 4
        for (int r = 0; r < 16; r++) {
            int row = rbase + r;
            int rs = (row < N_NODES) ? row : N_NODES - 1;
            float x0 = __ldg(&x[2 * rs]), x1 = __ldg(&x[2 * rs + 1]);
            float4 h;
            h.x = fmaxf(fmaf(x0, w0.x, fmaf(x1, w1.x, b.x)), 0.f);
            h.y = fmaxf(fmaf(x0, w0.y, fmaf(x1, w1.y, b.y)), 0.f);
            h.z = fmaxf(fmaf(x0, w0.z, fmaf(x1, w1.z, b.z)), 0.f);
            h.w = fmaxf(fmaf(x0, w0.w, fmaf(x1, w1.w, b.w)), 0.f);
            if (row < N_NODES) H04[(size_t)row * 32 + lane] = h;
            *reinterpret_cast<float4*>(sw + r * SM_STRIDE + 4 * lane) = h;
        }
    } else {
        float4 ba = ((const float4*)d_bnA)[lane];
        float4 bc = ((const float4*)d_bnC)[lane];
        const float4* A4 = reinterpret_cast<const float4*>(d_agg);
        const float4* HI4 = reinterpret_cast<const float4*>(hbuf(hin_sel));
        float4* HO4 = reinterpret_cast<float4*>(hbuf(hout_sel));
        #pragma unroll 4
        for (int r = 0; r < 16; r++) {
            int row = rbase + r;
            int rs = (row < N_NODES) ? row : N_NODES - 1;
            float4 v = A4[(size_t)rs * 32 + lane];
            float4 ho = HI4[(size_t)rs * 32 + lane];
            float4 h;
            h.x = fmaxf(fmaf(ba.x, v.x, bc.x), 0.f) + ho.x;
            h.y = fmaxf(fmaf(ba.y, v.y, bc.y), 0.f) + ho.y;
            h.z = fmaxf(fmaf(ba.z, v.z, bc.z), 0.f) + ho.z;
            h.w = fmaxf(fmaf(ba.w, v.w, bc.w), 0.f) + ho.w;
            if (row < N_NODES) HO4[(size_t)row * 32 + lane] = h;
            *reinterpret_cast<float4*>(sw + r * SM_STRIDE + 4 * lane) = h;
        }
    }
    __syncwarp();

    // ---- phase 2: A fragments (split bf16), 8 k-tiles ----
    const int g = lane >> 2, t = lane & 3;
    const float* r0p = sw + g * SM_STRIDE;
    const float* r1p = sw + (g + 8) * SM_STRIDE;
    uint32_t ah[32], al[32];
    #pragma unroll
    for (int kt = 0; kt < 8; kt++) {
        float2 p0 = *reinterpret_cast<const float2*>(r0p + 16 * kt + 2 * t);
        float2 p1 = *reinterpret_cast<const float2*>(r1p + 16 * kt + 2 * t);
        float2 p2 = *reinterpret_cast<const float2*>(r0p + 16 * kt + 2 * t + 8);
        float2 p3 = *reinterpret_cast<const float2*>(r1p + 16 * kt + 2 * t + 8);
        split2(p0.x, p0.y, ah[4 * kt + 0], al[4 * kt + 0]);
        split2(p1.x, p1.y, ah[4 * kt + 1], al[4 * kt + 1]);
        split2(p2.x, p2.y, ah[4 * kt + 2], al[4 * kt + 2]);
        split2(p3.x, p3.y, ah[4 * kt + 3], al[4 * kt + 3]);
    }

    // ---- phase 3: mma over 16 n-tiles (2 at a time), 3-pass split bf16; fp16 epilogue ----
    const uint4* Wf = &d_Wfrag[layer * 128 * 32];
    int row0 = rbase + g, row1 = rbase + g + 8;
    float dv0 = d_dinv[(row0 < N_NODES) ? row0 : 0];
    float dv1 = d_dinv[(row1 < N_NODES) ? row1 : 0];

    #pragma unroll
    for (int ntp = 0; ntp < 8; ntp++) {
        float c0[4] = {0.f, 0.f, 0.f, 0.f};
        float c1[4] = {0.f, 0.f, 0.f, 0.f};
        #pragma unroll
        for (int kt = 0; kt < 8; kt++) {
            uint4 B0 = __ldg(&Wf[(kt * 16 + 2 * ntp) * 32 + lane]);
            uint4 B1 = __ldg(&Wf[(kt * 16 + 2 * ntp + 1) * 32 + lane]);
            uint32_t a0 = ah[4 * kt], a1 = ah[4 * kt + 1], a2 = ah[4 * kt + 2], a3 = ah[4 * kt + 3];
            uint32_t l0 = al[4 * kt], l1 = al[4 * kt + 1], l2 = al[4 * kt + 2], l3 = al[4 * kt + 3];
            mma_bf16(c0, a0, a1, a2, a3, B0.x, B0.y);   // Ah * Bh
            mma_bf16(c0, l0, l1, l2, l3, B0.x, B0.y);   // Al * Bh
            mma_bf16(c0, a0, a1, a2, a3, B0.z, B0.w);   // Ah * Bl
            mma_bf16(c1, a0, a1, a2, a3, B1.x, B1.y);
            mma_bf16(c1, l0, l1, l2, l3, B1.x, B1.y);
            mma_bf16(c1, a0, a1, a2, a3, B1.z, B1.w);
        }
        int col0 = (2 * ntp) * 8 + 2 * t;
        int col1 = (2 * ntp + 1) * 8 + 2 * t;
        if (row0 < N_NODES) {
            *reinterpret_cast<__half2*>(d_g + (size_t)row0 * 128 + col0) =
                __floats2half2_rn(c0[0] * dv0, c0[1] * dv0);
            *reinterpret_cast<__half2*>(d_g + (size_t)row0 * 128 + col1) =
                __floats2half2_rn(c1[0] * dv0, c1[1] * dv0);
        }
        if (row1 < N_NODES) {
            *reinterpret_cast<__half2*>(d_g + (size_t)row1 * 128 + col0) =
                __floats2half2_rn(c0[2] * dv1, c0[3] * dv1);
            *reinterpret_cast<__half2*>(d_g + (size_t)row1 * 128 + col1) =
                __floats2half2_rn(c1[2] * dv1, c1[3] * dv1);
        }
    }
}

// ---------------- aggregation: agg[i] = dinv[i]*(sum_in g[src] + g[i]); BN partials ---
// d_g fp16 gather; d_agg fp32 (streaming store keeps fp16 table L2-resident)
__global__ void k_aggregate() {
    __shared__ float sS[HID];
    __shared__ float sQ[HID];
    if (threadIdx.x < HID) { sS[threadIdx.x] = 0.f; sQ[threadIdx.x] = 0.f; }
    __syncthreads();

    const int lane = threadIdx.x & 31;
    const int gwid = (blockIdx.x * blockDim.x + threadIdx.x) >> 5;
    const int nwarps = (gridDim.x * blockDim.x) >> 5;
    const uint2* g2 = reinterpret_cast<const uint2*>(d_g);
    float4* agg4 = reinterpret_cast<float4*>(d_agg);

    float4 lsum = make_float4(0.f, 0.f, 0.f, 0.f);
    float4 lsq  = make_float4(0.f, 0.f, 0.f, 0.f);

    for (int i = gwid; i < N_NODES; i += nwarps) {
        float4 acc = make_float4(0.f, 0.f, 0.f, 0.f);
        addh4(acc, __ldg(&g2[(size_t)i * 32 + lane]));   // self loop
        int e0 = d_rowptr[i], e1 = d_rowptr[i + 1];
        int e = e0;
        for (; e + 4 <= e1; e += 4) {                    // unroll x4 for gather MLP
            int s0 = __ldg(&d_col[e]);
            int s1 = __ldg(&d_col[e + 1]);
            int s2 = __ldg(&d_col[e + 2]);
            int s3 = __ldg(&d_col[e + 3]);
            uint2 v0 = __ldg(&g2[(size_t)s0 * 32 + lane]);
            uint2 v1 = __ldg(&g2[(size_t)s1 * 32 + lane]);
            uint2 v2 = __ldg(&g2[(size_t)s2 * 32 + lane]);
            uint2 v3 = __ldg(&g2[(size_t)s3 * 32 + lane]);
            addh4(acc, v0); addh4(acc, v1); addh4(acc, v2); addh4(acc, v3);
        }
        for (; e < e1; e++) {
            int s0 = __ldg(&d_col[e]);
            addh4(acc, __ldg(&g2[(size_t)s0 * 32 + lane]));
        }
        float dv = d_dinv[i];
        acc.x *= dv; acc.y *= dv; acc.z *= dv; acc.w *= dv;
        __stcs(&agg4[(size_t)i * 32 + lane], acc);       // streaming store, no reuse
        lsum.x += acc.x; lsum.y += acc.y; lsum.z += acc.z; lsum.w += acc.w;
        lsq.x = fmaf(acc.x, acc.x, lsq.x);
        lsq.y = fmaf(acc.y, acc.y, lsq.y);
        lsq.z = fmaf(acc.z, acc.z, lsq.z);
        lsq.w = fmaf(acc.w, acc.w, lsq.w);
    }
    int f = 4 * lane;
    atomicAdd(&sS[f + 0], lsum.x); atomicAdd(&sS[f + 1], lsum.y);
    atomicAdd(&sS[f + 2], lsum.z); atomicAdd(&sS[f + 3], lsum.w);
    atomicAdd(&sQ[f + 0], lsq.x);  atomicAdd(&sQ[f + 1], lsq.y);
    atomicAdd(&sQ[f + 2], lsq.z);  atomicAdd(&sQ[f + 3], lsq.w);
    __syncthreads();
    if (threadIdx.x < HID) {
        atomicAdd(&d_bnSum[threadIdx.x], (double)sS[threadIdx.x]);
        atomicAdd(&d_bnSqs[threadIdx.x], (double)sQ[threadIdx.x]);
    }
}

// ---------------- BN coeffs: a = gamma*rsqrt(var+eps), c = beta - mean*a; zero accs ----
__global__ void k_bn_finalize(const float* __restrict__ gamma,
                              const float* __restrict__ beta, int nfeat) {
    int t = threadIdx.x;
    if (t < nfeat) {
        double mean = d_bnSum[t] / (double)N_NODES;
        double var  = d_bnSqs[t] / (double)N_NODES - mean * mean;
        float a = gamma[t] * rsqrtf((float)var + EPS);
        d_bnA[t] = a;
        d_bnC[t] = beta[t] - (float)mean * a;
        d_bnSum[t] = 0.0;       // ready for next layer's stats
        d_bnSqs[t] = 0.0;
    }
}

// ---------------- head gemm: h3 = relu(a*agg+c)+h2 inline; ff = h3@Wf1; BN stats ------
// ff written as fp32 into d_g's storage (disjoint in time from fp16 use)
__global__ void k_gemm32_fused(const float* __restrict__ W, int hin_sel) {
    __shared__ float sW[HID * 32];
    __shared__ float sS[32];
    __shared__ float sQ[32];
    for (int i = threadIdx.x; i < HID * 32; i += blockDim.x) sW[i] = W[i];
    if (threadIdx.x < 32) { sS[threadIdx.x] = 0.f; sQ[threadIdx.x] = 0.f; }
    __syncthreads();
    const int lane = threadIdx.x & 31;
    const int gwid = (blockIdx.x * blockDim.x + threadIdx.x) >> 5;
    const int nwarps = (gridDim.x * blockDim.x) >> 5;
    const float4* A4 = reinterpret_cast<const float4*>(d_agg);
    const float4* HI4 = reinterpret_cast<const float4*>(hbuf(hin_sel));
    float* ff = reinterpret_cast<float*>(d_g);
    float4 ba = ((const float4*)d_bnA)[lane];
    float4 bc = ((const float4*)d_bnC)[lane];
    float s = 0.f, q = 0.f;

    for (int i = gwid; i < N_NODES; i += nwarps) {
        float4 v = A4[(size_t)i * 32 + lane];
        float4 ho = HI4[(size_t)i * 32 + lane];
        float4 h;
        h.x = fmaxf(fmaf(ba.x, v.x, bc.x), 0.f) + ho.x;
        h.y = fmaxf(fmaf(ba.y, v.y, bc.y), 0.f) + ho.y;
        h.z = fmaxf(fmaf(ba.z, v.z, bc.z), 0.f) + ho.z;
        h.w = fmaxf(fmaf(ba.w, v.w, bc.w), 0.f) + ho.w;
        float acc = 0.f;
        #pragma unroll 8
        for (int p = 0; p < 32; p++) {
            float sx = __shfl_sync(0xffffffffu, h.x, p);
            float sy = __shfl_sync(0xffffffffu, h.y, p);
            float sz = __shfl_sync(0xffffffffu, h.z, p);
            float sw = __shfl_sync(0xffffffffu, h.w, p);
            acc = fmaf(sx, sW[(4 * p + 0) * 32 + lane], acc);
            acc = fmaf(sy, sW[(4 * p + 1) * 32 + lane], acc);
            acc = fmaf(sz, sW[(4 * p + 2) * 32 + lane], acc);
            acc = fmaf(sw, sW[(4 * p + 3) * 32 + lane], acc);
        }
        ff[(size_t)i * 32 + lane] = acc;
        s += acc;
        q = fmaf(acc, acc, q);
    }
    atomicAdd(&sS[lane], s);
    atomicAdd(&sQ[lane], q);
    __syncthreads();
    if (threadIdx.x < 32) {
        atomicAdd(&d_bnSum[threadIdx.x], (double)sS[threadIdx.x]);
        atomicAdd(&d_bnSqs[threadIdx.x], (double)sQ[threadIdx.x]);
    }
}

// ---------------- out = tanh(relu(a*ff+c) @ Wf2 + bf2) ----------------
__global__ void k_out(const float* __restrict__ Wf2,
                      const float* __restrict__ bf2,
                      float* __restrict__ out) {
    __shared__ float sA[32], sC[32], sW[64], sB[2];
    int t = threadIdx.x;
    if (t < 32) { sA[t] = d_bnA[t]; sC[t] = d_bnC[t]; }
    if (t < 64) sW[t] = Wf2[t];
    if (t < 2) sB[t] = bf2[t];
    __syncthreads();
    int i = blockIdx.x * blockDim.x + t;
    if (i >= N_NODES) return;
    float a0 = sB[0], a1 = sB[1];
    const float4* f4 = reinterpret_cast<const float4*>(reinterpret_cast<const float*>(d_g) + (size_t)i * 32);
    #pragma unroll
    for (int j4 = 0; j4 < 8; j4++) {
        float4 v = f4[j4];
        int j = j4 * 4;
        float f;
        f = fmaxf(fmaf(sA[j + 0], v.x, sC[j + 0]), 0.f); a0 = fmaf(f, sW[2 * (j + 0)], a0); a1 = fmaf(f, sW[2 * (j + 0) + 1], a1);
        f = fmaxf(fmaf(sA[j + 1], v.y, sC[j + 1]), 0.f); a0 = fmaf(f, sW[2 * (j + 1)], a0); a1 = fmaf(f, sW[2 * (j + 1) + 1], a1);
        f = fmaxf(fmaf(sA[j + 2], v.z, sC[j + 2]), 0.f); a0 = fmaf(f, sW[2 * (j + 2)], a0); a1 = fmaf(f, sW[2 * (j + 2) + 1], a1);
        f = fmaxf(fmaf(sA[j + 3], v.w, sC[j + 3]), 0.f); a0 = fmaf(f, sW[2 * (j + 3)], a0); a1 = fmaf(f, sW[2 * (j + 3) + 1], a1);
    }
    out[2 * i]     = tanhf(a0);
    out[2 * i + 1] = tanhf(a1);
}

// ---------------- launch ----------------
extern "C" void kernel_launch(void* const* d_in, const int* in_sizes, int n_in,
                              void* d_out, int out_size) {
    const float* x    = (const float*)d_in[0];
    const int*   ei   = (const int*)d_in[1];
    const float* We   = (const float*)d_in[2];
    const float* be   = (const float*)d_in[3];
    const float* W1   = (const float*)d_in[4];
    const float* g1   = (const float*)d_in[6];
    const float* bt1  = (const float*)d_in[7];
    const float* W2   = (const float*)d_in[8];
    const float* g2   = (const float*)d_in[10];
    const float* bt2  = (const float*)d_in[11];
    const float* W3   = (const float*)d_in[12];
    const float* g3   = (const float*)d_in[14];
    const float* bt3  = (const float*)d_in[15];
    const float* Wf1  = (const float*)d_in[16];
    const float* gf   = (const float*)d_in[18];
    const float* btf  = (const float*)d_in[19];
    const float* Wf2  = (const float*)d_in[20];
    const float* bf2  = (const float*)d_in[21];
    float* out = (float*)d_out;
    // (b1/b2/b3/bf1 unused: uniform per-feature bias cancels inside BatchNorm)

    cudaFuncSetAttribute(k_mma_gemm, cudaFuncAttributeMaxDynamicSharedMemorySize, SMEM_MMA);

    const int nb_scan = (N_NODES + 1023) / 1024;   // 98
    const int GB = 592;

    // graph preprocessing: degree -> dinv, CSC build ; B-fragment prep
    k_zero_counts<<<(N_NODES + 255) / 256, 256>>>();
    k_count<<<(N_EDGES + 255) / 256, 256>>>(ei);
    k_dinv<<<(N_NODES + 255) / 256, 256>>>();
    k_scan_local<<<nb_scan, 1024>>>();
    k_scan_bsums<<<1, 128>>>(nb_scan);
    k_scan_add<<<nb_scan, 1024>>>();
    k_fill<<<(N_EDGES + 255) / 256, 256>>>(ei);
    k_prep_wfrag<<<48, 256>>>(W1, W2, W3);

    // block 1: encoder fused; h0 -> g
    k_mma_gemm<<<N_TILES, 256, SMEM_MMA>>>(x, We, be, 0, 0, 0, 1);
    k_aggregate<<<GB, 256>>>();
    k_bn_finalize<<<1, 128>>>(g1, bt1, HID);

    // block 2: bnrelu(block1) fused; h0 -> h1 -> g
    k_mma_gemm<<<N_TILES, 256, SMEM_MMA>>>(nullptr, nullptr, nullptr, 1, 0, 1, 0);
    k_aggregate<<<GB, 256>>>();
    k_bn_finalize<<<1, 128>>>(g2, bt2, HID);

    // block 3: bnrelu(block2) fused; h1 -> h0 -> g
    k_mma_gemm<<<N_TILES, 256, SMEM_MMA>>>(nullptr, nullptr, nullptr, 2, 1, 0, 0);
    k_aggregate<<<GB, 256>>>();
    k_bn_finalize<<<1, 128>>>(g3, bt3, HID);

    // head: bnrelu(block3) fused; h0 -> h3 (regs) -> ff, stats fused
    k_gemm32_fused<<<GB, 256>>>(Wf1, 0);
    k_bn_finalize<<<1, 128>>>(gf, btf, 32);
    k_out<<<(N_NODES + 127) / 128, 128>>>(Wf2, bf2, out);

    (void)in_sizes; (void)n_in; (void)out_size;
}

// round 14
// speedup vs baseline: 1.1893x; 1.1893x over previous
#include <cuda_runtime.h>
#include <cuda_fp16.h>
#include <math.h>
#include <stdint.h>

#define N_NODES 100000
#define N_EDGES 1600000
#define HID 128
#define EPS 1e-5f
#define N_TILES 782          // ceil(100000/128)
#define SM_STRIDE 136        // floats per staged row; 136 % 32 == 8 -> conflict-free frag LDS
#define SMEM_MMA (8 * 16 * SM_STRIDE * 4)   // 69632 B

// ---------------- scratch (device globals; referenced ONLY in device code) ----------------
__device__ float  d_h0[N_NODES * HID];
__device__ float  d_h1[N_NODES * HID];
__device__ __half d_g [N_NODES * HID];   // fp16 gather table; head reuses bytes as ff[N,32] fp32
__device__ float  d_agg[N_NODES * HID];  // fp32 aggregate stream (fp16 here compounds error -> fails gate)
__device__ float  d_dinv[N_NODES];
__device__ int    d_cnt[N_NODES];
__device__ int    d_cursor[N_NODES];
__device__ int    d_rowptr[N_NODES + 1];
__device__ int    d_col[N_EDGES];
__device__ int    d_bsums[128];
// 4 rotating BN stat buffers: 0,1,2 = blocks 1..3 (HID feats), 3 = head (32 feats)
__device__ double d_bnSum[4][HID];
__device__ double d_bnSqs[4][HID];
// B-fragment images: layers 0..2 at [(L*128 + kt*16 + nt)*32], head (Wf1) at [(384 + kt*4 + nt)*32]
__device__ uint4  d_Wfrag[(3 * 128 + 32) * 32];

// ---------------- helpers ----------------
__device__ __forceinline__ float* hbuf(int sel) { return sel == 0 ? d_h0 : d_h1; }

__device__ __forceinline__ uint32_t pack_bf16x2(float lo, float hi) {
    uint32_t d;
    asm("cvt.rn.bf16x2.f32 %0, %2, %1;" : "=r"(d) : "f"(lo), "f"(hi));
    return d;
}
__device__ __forceinline__ float bf_lo(uint32_t v) { return __uint_as_float(v << 16); }
__device__ __forceinline__ float bf_hi(uint32_t v) { return __uint_as_float(v & 0xffff0000u); }

__device__ __forceinline__ void split2(float a, float b, uint32_t& hi, uint32_t& lo) {
    hi = pack_bf16x2(a, b);
    lo = pack_bf16x2(a - bf_lo(hi), b - bf_hi(hi));
}

__device__ __forceinline__ void mma_bf16(float c[4], uint32_t a0, uint32_t a1,
                                         uint32_t a2, uint32_t a3,
                                         uint32_t b0, uint32_t b1) {
    asm volatile(
        "mma.sync.aligned.m16n8k16.row.col.f32.bf16.bf16.f32 "
        "{%0,%1,%2,%3}, {%4,%5,%6,%7}, {%8,%9}, {%0,%1,%2,%3};"
        : "+f"(c[0]), "+f"(c[1]), "+f"(c[2]), "+f"(c[3])
        : "r"(a0), "r"(a1), "r"(a2), "r"(a3), "r"(b0), "r"(b1));
}

__device__ __forceinline__ void addh4(float4& a, uint2 v) {
    float2 f0 = __half22float2(*reinterpret_cast<const __half2*>(&v.x));
    float2 f1 = __half22float2(*reinterpret_cast<const __half2*>(&v.y));
    a.x += f0.x; a.y += f0.y; a.z += f1.x; a.w += f1.y;
}

// per-lane BN coefficients for features 4*lane..4*lane+3 from stat buffer rd
__device__ __forceinline__ void bn_coeffs4(int rd, int lane,
                                           const float* __restrict__ gamma,
                                           const float* __restrict__ beta,
                                           float4& A, float4& C) {
    const float invn = 1.0f / (float)N_NODES;
    float4 gm = __ldg(&((const float4*)gamma)[lane]);
    float4 bt = __ldg(&((const float4*)beta)[lane]);
    int f = 4 * lane;
    float m, v;
    m = (float)d_bnSum[rd][f + 0] * invn; v = (float)d_bnSqs[rd][f + 0] * invn - m * m;
    A.x = gm.x * rsqrtf(v + EPS); C.x = bt.x - m * A.x;
    m = (float)d_bnSum[rd][f + 1] * invn; v = (float)d_bnSqs[rd][f + 1] * invn - m * m;
    A.y = gm.y * rsqrtf(v + EPS); C.y = bt.y - m * A.y;
    m = (float)d_bnSum[rd][f + 2] * invn; v = (float)d_bnSqs[rd][f + 2] * invn - m * m;
    A.z = gm.z * rsqrtf(v + EPS); C.z = bt.z - m * A.z;
    m = (float)d_bnSum[rd][f + 3] * invn; v = (float)d_bnSqs[rd][f + 3] * invn - m * m;
    A.w = gm.w * rsqrtf(v + EPS); C.w = bt.w - m * A.w;
}

// ---------------- setup kernels ----------------
__global__ void k_zero_counts() {
    int i = blockIdx.x * blockDim.x + threadIdx.x;
    if (i < N_NODES) { d_cnt[i] = 0; d_cursor[i] = 0; }
}
__global__ void k_count(const int* __restrict__ ei) {
    int e = blockIdx.x * blockDim.x + threadIdx.x;
    if (e < N_EDGES) atomicAdd(&d_cnt[ei[N_EDGES + e]], 1);
}
__global__ void k_scan_local() {
    __shared__ int s[1024];
    int tid = threadIdx.x;
    int idx = blockIdx.x * 1024 + tid;
    int v = (idx < N_NODES) ? d_cnt[idx] : 0;
    if (idx < N_NODES) d_dinv[idx] = rsqrtf((float)v + 1.0f);   // fused dinv
    s[tid] = v;
    __syncthreads();
    for (int off = 1; off < 1024; off <<= 1) {
        int t = (tid >= off) ? s[tid - off] : 0;
        __syncthreads();
        s[tid] += t;
        __syncthreads();
    }
    if (idx < N_NODES) d_rowptr[idx] = s[tid] - v;   // exclusive
    if (tid == 1023) d_bsums[blockIdx.x] = s[1023];
}
__global__ void k_scan_bsums(int nb) {
    __shared__ int sb[128];
    int t = threadIdx.x;
    sb[t] = (t < nb) ? d_bsums[t] : 0;
    __syncthreads();
    if (t == 0) {
        int run = 0;
        for (int i = 0; i < nb; i++) { int x = sb[i]; sb[i] = run; run += x; }
        d_rowptr[N_NODES] = run;
    }
    __syncthreads();
    if (t < nb) d_bsums[t] = sb[t];
}
__global__ void k_scan_add() {
    int idx = blockIdx.x * 1024 + threadIdx.x;
    if (idx < N_NODES) d_rowptr[idx] += d_bsums[blockIdx.x];
}
__global__ void k_fill(const int* __restrict__ ei) {
    int e = blockIdx.x * blockDim.x + threadIdx.x;
    if (e < N_EDGES) {
        int s = ei[e];
        int d = ei[N_EDGES + e];
        int pos = d_rowptr[d] + atomicAdd(&d_cursor[d], 1);
        d_col[pos] = s;
    }
}

// ---------------- W prep: B fragments for 3 main layers (n=128) + head Wf1 (n=32) ------
__global__ void k_prep_wfrag(const float* __restrict__ W1,
                             const float* __restrict__ W2,
                             const float* __restrict__ W3,
                             const float* __restrict__ Wf1) {
    int idx = blockIdx.x * blockDim.x + threadIdx.x;
    if (idx >= 3 * 4096 + 1024) return;
    if (idx < 3 * 4096) {
        int lane = idx & 31;
        int nt = (idx >> 5) & 15;
        int kt = (idx >> 9) & 7;
        int L  = idx >> 12;
        const float* W = (L == 0) ? W1 : (L == 1) ? W2 : W3;
        int g = lane >> 2, t = lane & 3;
        int n = nt * 8 + g;
        int k0 = kt * 16 + 2 * t;
        int k1 = k0 + 8;
        uint32_t h0, l0, h1, l1;
        split2(W[k0 * 128 + n], W[(k0 + 1) * 128 + n], h0, l0);
        split2(W[k1 * 128 + n], W[(k1 + 1) * 128 + n], h1, l1);
        uint4 v; v.x = h0; v.y = h1; v.z = l0; v.w = l1;
        d_Wfrag[(L * 128 + kt * 16 + nt) * 32 + lane] = v;
    } else {
        int r = idx - 3 * 4096;
        int lane = r & 31;
        int nt = (r >> 5) & 3;
        int kt = (r >> 7) & 7;
        int g = lane >> 2, t = lane & 3;
        int n = nt * 8 + g;
        int k0 = kt * 16 + 2 * t;
        int k1 = k0 + 8;
        uint32_t h0, l0, h1, l1;
        split2(Wf1[k0 * 32 + n], Wf1[(k0 + 1) * 32 + n], h0, l0);
        split2(Wf1[k1 * 32 + n], Wf1[(k1 + 1) * 32 + n], h1, l1);
        uint4 v; v.x = h0; v.y = h1; v.z = l0; v.w = l1;
        d_Wfrag[(384 + kt * 4 + nt) * 32 + lane] = v;
    }
}

// ---------------- tensor GEMM: d_g(fp16) = dinv * (h_new @ W_layer) ----------------
// first=1: h_new = relu(x@We+be) (encoder); also zeroes all 4 BN stat buffers (CTA 0).
// first=0: h_new = relu(bnA*agg + bnC) + h_old, coeffs computed inline from buf bn_rd.
__global__ void __launch_bounds__(256, 2) k_mma_gemm(
    const float* __restrict__ x, const float* __restrict__ We,
    const float* __restrict__ be,
    const float* __restrict__ gamma, const float* __restrict__ beta,
    int layer, int hin_sel, int hout_sel, int first, int bn_rd) {
    extern __shared__ float smf[];
    const int lane = threadIdx.x & 31;
    const int wid = threadIdx.x >> 5;
    const int tile = blockIdx.x;
    float* sw = smf + wid * 16 * SM_STRIDE;
    const int rbase = tile * 128 + wid * 16;

    if (first && blockIdx.x == 0 && threadIdx.x < HID) {
        #pragma unroll
        for (int r = 0; r < 4; r++) {
            d_bnSum[r][threadIdx.x] = 0.0;
            d_bnSqs[r][threadIdx.x] = 0.0;
        }
    }

    // ---- phase 1: h_new for this warp's 16 rows ----
    if (first) {
        float4 w0 = __ldg(&((const float4*)We)[lane]);
        float4 w1 = __ldg(&((const float4*)We)[32 + lane]);
        float4 b  = __ldg(&((const float4*)be)[lane]);
        float4* H04 = reinterpret_cast<float4*>(d_h0);
        #pragma unroll 4
        for (int r = 0; r < 16; r++) {
            int row = rbase + r;
            int rs = (row < N_NODES) ? row : N_NODES - 1;
            float x0 = __ldg(&x[2 * rs]), x1 = __ldg(&x[2 * rs + 1]);
            float4 h;
            h.x = fmaxf(fmaf(x0, w0.x, fmaf(x1, w1.x, b.x)), 0.f);
            h.y = fmaxf(fmaf(x0, w0.y, fmaf(x1, w1.y, b.y)), 0.f);
            h.z = fmaxf(fmaf(x0, w0.z, fmaf(x1, w1.z, b.z)), 0.f);
            h.w = fmaxf(fmaf(x0, w0.w, fmaf(x1, w1.w, b.w)), 0.f);
            if (row < N_NODES) H04[(size_t)row * 32 + lane] = h;
            *reinterpret_cast<float4*>(sw + r * SM_STRIDE + 4 * lane) = h;
        }
    } else {
        float4 ba, bc;
        bn_coeffs4(bn_rd, lane, gamma, beta, ba, bc);
        const float4* A4 = reinterpret_cast<const float4*>(d_agg);
        const float4* HI4 = reinterpret_cast<const float4*>(hbuf(hin_sel));
        float4* HO4 = reinterpret_cast<float4*>(hbuf(hout_sel));
        #pragma unroll 4
        for (int r = 0; r < 16; r++) {
            int row = rbase + r;
            int rs = (row < N_NODES) ? row : N_NODES - 1;
            float4 v = A4[(size_t)rs * 32 + lane];
            float4 ho = HI4[(size_t)rs * 32 + lane];
            float4 h;
            h.x = fmaxf(fmaf(ba.x, v.x, bc.x), 0.f) + ho.x;
            h.y = fmaxf(fmaf(ba.y, v.y, bc.y), 0.f) + ho.y;
            h.z = fmaxf(fmaf(ba.z, v.z, bc.z), 0.f) + ho.z;
            h.w = fmaxf(fmaf(ba.w, v.w, bc.w), 0.f) + ho.w;
            if (row < N_NODES) HO4[(size_t)row * 32 + lane] = h;
            *reinterpret_cast<float4*>(sw + r * SM_STRIDE + 4 * lane) = h;
        }
    }
    __syncwarp();

    // ---- phase 2: A fragments (split bf16), 8 k-tiles ----
    const int g = lane >> 2, t = lane & 3;
    const float* r0p = sw + g * SM_STRIDE;
    const float* r1p = sw + (g + 8) * SM_STRIDE;
    uint32_t ah[32], al[32];
    #pragma unroll
    for (int kt = 0; kt < 8; kt++) {
        float2 p0 = *reinterpret_cast<const float2*>(r0p + 16 * kt + 2 * t);
        float2 p1 = *reinterpret_cast<const float2*>(r1p + 16 * kt + 2 * t);
        float2 p2 = *reinterpret_cast<const float2*>(r0p + 16 * kt + 2 * t + 8);
        float2 p3 = *reinterpret_cast<const float2*>(r1p + 16 * kt + 2 * t + 8);
        split2(p0.x, p0.y, ah[4 * kt + 0], al[4 * kt + 0]);
        split2(p1.x, p1.y, ah[4 * kt + 1], al[4 * kt + 1]);
        split2(p2.x, p2.y, ah[4 * kt + 2], al[4 * kt + 2]);
        split2(p3.x, p3.y, ah[4 * kt + 3], al[4 * kt + 3]);
    }

    // ---- phase 3: mma over 16 n-tiles (2 at a time), 3-pass split bf16; fp16 epilogue ----
    const uint4* Wf = &d_Wfrag[layer * 128 * 32];
    int row0 = rbase + g, row1 = rbase + g + 8;
    float dv0 = d_dinv[(row0 < N_NODES) ? row0 : 0];
    float dv1 = d_dinv[(row1 < N_NODES) ? row1 : 0];

    #pragma unroll
    for (int ntp = 0; ntp < 8; ntp++) {
        float c0[4] = {0.f, 0.f, 0.f, 0.f};
        float c1[4] = {0.f, 0.f, 0.f, 0.f};
        #pragma unroll
        for (int kt = 0; kt < 8; kt++) {
            uint4 B0 = __ldg(&Wf[(kt * 16 + 2 * ntp) * 32 + lane]);
            uint4 B1 = __ldg(&Wf[(kt * 16 + 2 * ntp + 1) * 32 + lane]);
            uint32_t a0 = ah[4 * kt], a1 = ah[4 * kt + 1], a2 = ah[4 * kt + 2], a3 = ah[4 * kt + 3];
            uint32_t l0 = al[4 * kt], l1 = al[4 * kt + 1], l2 = al[4 * kt + 2], l3 = al[4 * kt + 3];
            mma_bf16(c0, a0, a1, a2, a3, B0.x, B0.y);   // Ah * Bh
            mma_bf16(c0, l0, l1, l2, l3, B0.x, B0.y);   // Al * Bh
            mma_bf16(c0, a0, a1, a2, a3, B0.z, B0.w);   // Ah * Bl
            mma_bf16(c1, a0, a1, a2, a3, B1.x, B1.y);
            mma_bf16(c1, l0, l1, l2, l3, B1.x, B1.y);
            mma_bf16(c1, a0, a1, a2, a3, B1.z, B1.w);
        }
        int col0 = (2 * ntp) * 8 + 2 * t;
        int col1 = (2 * ntp + 1) * 8 + 2 * t;
        if (row0 < N_NODES) {
            *reinterpret_cast<__half2*>(d_g + (size_t)row0 * 128 + col0) =
                __floats2half2_rn(c0[0] * dv0, c0[1] * dv0);
            *reinterpret_cast<__half2*>(d_g + (size_t)row0 * 128 + col1) =
                __floats2half2_rn(c1[0] * dv0, c1[1] * dv0);
        }
        if (row1 < N_NODES) {
            *reinterpret_cast<__half2*>(d_g + (size_t)row1 * 128 + col0) =
                __floats2half2_rn(c0[2] * dv1, c0[3] * dv1);
            *reinterpret_cast<__half2*>(d_g + (size_t)row1 * 128 + col1) =
                __floats2half2_rn(c1[2] * dv1, c1[3] * dv1);
        }
    }
}

// ---------------- aggregation: agg[i] = dinv[i]*(sum_in g[src] + g[i]); BN partials ---
__global__ void k_aggregate(int bw) {
    __shared__ float sS[HID];
    __shared__ float sQ[HID];
    if (threadIdx.x < HID) { sS[threadIdx.x] = 0.f; sQ[threadIdx.x] = 0.f; }
    __syncthreads();

    const int lane = threadIdx.x & 31;
    const int gwid = (blockIdx.x * blockDim.x + threadIdx.x) >> 5;
    const int nwarps = (gridDim.x * blockDim.x) >> 5;
    const uint2* g2 = reinterpret_cast<const uint2*>(d_g);
    float4* agg4 = reinterpret_cast<float4*>(d_agg);

    float4 lsum = make_float4(0.f, 0.f, 0.f, 0.f);
    float4 lsq  = make_float4(0.f, 0.f, 0.f, 0.f);

    for (int i = gwid; i < N_NODES; i += nwarps) {
        float4 acc = make_float4(0.f, 0.f, 0.f, 0.f);
        addh4(acc, __ldg(&g2[(size_t)i * 32 + lane]));   // self loop
        int e0 = d_rowptr[i], e1 = d_rowptr[i + 1];
        int e = e0;
        for (; e + 4 <= e1; e += 4) {
            int s0 = __ldg(&d_col[e]);
            int s1 = __ldg(&d_col[e + 1]);
            int s2 = __ldg(&d_col[e + 2]);
            int s3 = __ldg(&d_col[e + 3]);
            uint2 v0 = __ldg(&g2[(size_t)s0 * 32 + lane]);
            uint2 v1 = __ldg(&g2[(size_t)s1 * 32 + lane]);
            uint2 v2 = __ldg(&g2[(size_t)s2 * 32 + lane]);
            uint2 v3 = __ldg(&g2[(size_t)s3 * 32 + lane]);
            addh4(acc, v0); addh4(acc, v1); addh4(acc, v2); addh4(acc, v3);
        }
        for (; e < e1; e++) {
            int s0 = __ldg(&d_col[e]);
            addh4(acc, __ldg(&g2[(size_t)s0 * 32 + lane]));
        }
        float dv = d_dinv[i];
        acc.x *= dv; acc.y *= dv; acc.z *= dv; acc.w *= dv;
        __stcs(&agg4[(size_t)i * 32 + lane], acc);       // streaming store, no reuse
        lsum.x += acc.x; lsum.y += acc.y; lsum.z += acc.z; lsum.w += acc.w;
        lsq.x = fmaf(acc.x, acc.x, lsq.x);
        lsq.y = fmaf(acc.y, acc.y, lsq.y);
        lsq.z = fmaf(acc.z, acc.z, lsq.z);
        lsq.w = fmaf(acc.w, acc.w, lsq.w);
    }
    int f = 4 * lane;
    atomicAdd(&sS[f + 0], lsum.x); atomicAdd(&sS[f + 1], lsum.y);
    atomicAdd(&sS[f + 2], lsum.z); atomicAdd(&sS[f + 3], lsum.w);
    atomicAdd(&sQ[f + 0], lsq.x);  atomicAdd(&sQ[f + 1], lsq.y);
    atomicAdd(&sQ[f + 2], lsq.z);  atomicAdd(&sQ[f + 3], lsq.w);
    __syncthreads();
    if (threadIdx.x < HID) {
        atomicAdd(&d_bnSum[bw][threadIdx.x], (double)sS[threadIdx.x]);
        atomicAdd(&d_bnSqs[bw][threadIdx.x], (double)sQ[threadIdx.x]);
    }
}

// ---------------- head: h3 = BN3(agg)+h2 (smem only); ff = h3@Wf1 via mma; stats->buf3 --
__global__ void __launch_bounds__(256, 2) k_mma_head(
    const float* __restrict__ gamma, const float* __restrict__ beta,
    int hin_sel, int bn_rd) {
    extern __shared__ float smf[];
    __shared__ float sS[32];
    __shared__ float sQ[32];
    const int lane = threadIdx.x & 31;
    const int wid = threadIdx.x >> 5;
    const int tile = blockIdx.x;
    float* sw = smf + wid * 16 * SM_STRIDE;
    const int rbase = tile * 128 + wid * 16;

    if (threadIdx.x < 32) { sS[threadIdx.x] = 0.f; sQ[threadIdx.x] = 0.f; }
    __syncthreads();

    // ---- phase 1: h3 rows into smem (no gmem store) ----
    {
        float4 ba, bc;
        bn_coeffs4(bn_rd, lane, gamma, beta, ba, bc);
        const float4* A4 = reinterpret_cast<const float4*>(d_agg);
        const float4* HI4 = reinterpret_cast<const float4*>(hbuf(hin_sel));
        #pragma unroll 4
        for (int r = 0; r < 16; r++) {
            int row = rbase + r;
            int rs = (row < N_NODES) ? row : N_NODES - 1;
            float4 v = A4[(size_t)rs * 32 + lane];
            float4 ho = HI4[(size_t)rs * 32 + lane];
            float4 h;
            h.x = fmaxf(fmaf(ba.x, v.x, bc.x), 0.f) + ho.x;
            h.y = fmaxf(fmaf(ba.y, v.y, bc.y), 0.f) + ho.y;
            h.z = fmaxf(fmaf(ba.z, v.z, bc.z), 0.f) + ho.z;
            h.w = fmaxf(fmaf(ba.w, v.w, bc.w), 0.f) + ho.w;
            *reinterpret_cast<float4*>(sw + r * SM_STRIDE + 4 * lane) = h;
        }
    }
    __syncwarp();

    // ---- phase 2: A fragments ----
    const int g = lane >> 2, t = lane & 3;
    const float* r0p = sw + g * SM_STRIDE;
    const float* r1p = sw + (g + 8) * SM_STRIDE;
    uint32_t ah[32], al[32];
    #pragma unroll
    for (int kt = 0; kt < 8; kt++) {
        float2 p0 = *reinterpret_cast<const float2*>(r0p + 16 * kt + 2 * t);
        float2 p1 = *reinterpret_cast<const float2*>(r1p + 16 * kt + 2 * t);
        float2 p2 = *reinterpret_cast<const float2*>(r0p + 16 * kt + 2 * t + 8);
        float2 p3 = *reinterpret_cast<const float2*>(r1p + 16 * kt + 2 * t + 8);
        split2(p0.x, p0.y, ah[4 * kt + 0], al[4 * kt + 0]);
        split2(p1.x, p1.y, ah[4 * kt + 1], al[4 * kt + 1]);
        split2(p2.x, p2.y, ah[4 * kt + 2], al[4 * kt + 2]);
        split2(p3.x, p3.y, ah[4 * kt + 3], al[4 * kt + 3]);
    }

    // ---- phase 3: N=32 -> 2 ntp iterations; ff fp32 into d_g bytes; local stats ----
    const uint4* Wf = &d_Wfrag[384 * 32];
    float* ff = reinterpret_cast<float*>(d_g);
    int row0 = rbase + g, row1 = rbase + g + 8;
    bool v0 = row0 < N_NODES, v1 = row1 < N_NODES;
    float sl[8] = {0, 0, 0, 0, 0, 0, 0, 0};
    float ql[8] = {0, 0, 0, 0, 0, 0, 0, 0};

    #pragma unroll
    for (int ntp = 0; ntp < 2; ntp++) {
        float c0[4] = {0.f, 0.f, 0.f, 0.f};
        float c1[4] = {0.f, 0.f, 0.f, 0.f};
        #pragma unroll
        for (int kt = 0; kt < 8; kt++) {
            uint4 B0 = __ldg(&Wf[(kt * 4 + 2 * ntp) * 32 + lane]);
            uint4 B1 = __ldg(&Wf[(kt * 4 + 2 * ntp + 1) * 32 + lane]);
            uint32_t a0 = ah[4 * kt], a1 = ah[4 * kt + 1], a2 = ah[4 * kt + 2], a3 = ah[4 * kt + 3];
            uint32_t l0 = al[4 * kt], l1 = al[4 * kt + 1], l2 = al[4 * kt + 2], l3 = al[4 * kt + 3];
            mma_bf16(c0, a0, a1, a2, a3, B0.x, B0.y);
            mma_bf16(c0, l0, l1, l2, l3, B0.x, B0.y);
            mma_bf16(c0, a0, a1, a2, a3, B0.z, B0.w);
            mma_bf16(c1, a0, a1, a2, a3, B1.x, B1.y);
            mma_bf16(c1, l0, l1, l2, l3, B1.x, B1.y);
            mma_bf16(c1, a0, a1, a2, a3, B1.z, B1.w);
        }
        int col0 = (2 * ntp) * 8 + 2 * t;
        int col1 = col0 + 8;
        if (v0) {
            *reinterpret_cast<float2*>(ff + (size_t)row0 * 32 + col0) = make_float2(c0[0], c0[1]);
            *reinterpret_cast<float2*>(ff + (size_t)row0 * 32 + col1) = make_float2(c1[0], c1[1]);
            sl[4 * ntp + 0] += c0[0]; ql[4 * ntp + 0] += c0[0] * c0[0];
            sl[4 * ntp + 1] += c0[1]; ql[4 * ntp + 1] += c0[1] * c0[1];
            sl[4 * ntp + 2] += c1[0]; ql[4 * ntp + 2] += c1[0] * c1[0];
            sl[4 * ntp + 3] += c1[1]; ql[4 * ntp + 3] += c1[1] * c1[1];
        }
        if (v1) {
            *reinterpret_cast<float2*>(ff + (size_t)row1 * 32 + col0) = make_float2(c0[2], c0[3]);
            *reinterpret_cast<float2*>(ff + (size_t)row1 * 32 + col1) = make_float2(c1[2], c1[3]);
            sl[4 * ntp + 0] += c0[2]; ql[4 * ntp + 0] += c0[2] * c0[2];
            sl[4 * ntp + 1] += c0[3]; ql[4 * ntp + 1] += c0[3] * c0[3];
            sl[4 * ntp + 2] += c1[2]; ql[4 * ntp + 2] += c1[2] * c1[2];
            sl[4 * ntp + 3] += c1[3]; ql[4 * ntp + 3] += c1[3] * c1[3];
        }
    }

    // reduce over g (lanes xor 4,8,16), then lanes 0..3 (t==lane) hold totals
    #pragma unroll
    for (int off = 4; off < 32; off <<= 1) {
        #pragma unroll
        for (int j = 0; j < 8; j++) {
            sl[j] += __shfl_xor_sync(0xffffffffu, sl[j], off);
            ql[j] += __shfl_xor_sync(0xffffffffu, ql[j], off);
        }
    }
    if (lane < 4) {
        #pragma unroll
        for (int j = 0; j < 8; j++) {
            // j = 4*ntp + k : feature = 16*ntp + 8*(k>>1) + 2*lane + (k&1)
            int ntp = j >> 2, k = j & 3;
            int feat = 16 * ntp + 8 * (k >> 1) + 2 * lane + (k & 1);
            atomicAdd(&sS[feat], sl[j]);
            atomicAdd(&sQ[feat], ql[j]);
        }
    }
    __syncthreads();
    if (threadIdx.x < 32) {
        atomicAdd(&d_bnSum[3][threadIdx.x], (double)sS[threadIdx.x]);
        atomicAdd(&d_bnSqs[3][threadIdx.x], (double)sQ[threadIdx.x]);
    }
}

// ---------------- out = tanh(relu(a*ff+c) @ Wf2 + bf2), BN coeffs inline from buf3 ------
__global__ void k_out(const float* __restrict__ gf, const float* __restrict__ btf,
                      const float* __restrict__ Wf2,
                      const float* __restrict__ bf2,
                      float* __restrict__ out) {
    __shared__ float sA[32], sC[32], sW[64], sB[2];
    int t = threadIdx.x;
    if (t < 32) {
        const float invn = 1.0f / (float)N_NODES;
        float m = (float)d_bnSum[3][t] * invn;
        float v = (float)d_bnSqs[3][t] * invn - m * m;
        float a = __ldg(&gf[t]) * rsqrtf(v + EPS);
        sA[t] = a;
        sC[t] = __ldg(&btf[t]) - m * a;
    }
    if (t < 64) sW[t] = Wf2[t];
    if (t < 2) sB[t] = bf2[t];
    __syncthreads();
    int i = blockIdx.x * blockDim.x + t;
    if (i >= N_NODES) return;
    float a0 = sB[0], a1 = sB[1];
    const float4* f4 = reinterpret_cast<const float4*>(reinterpret_cast<const float*>(d_g) + (size_t)i * 32);
    #pragma unroll
    for (int j4 = 0; j4 < 8; j4++) {
        float4 v = f4[j4];
        int j = j4 * 4;
        float f;
        f = fmaxf(fmaf(sA[j + 0], v.x, sC[j + 0]), 0.f); a0 = fmaf(f, sW[2 * (j + 0)], a0); a1 = fmaf(f, sW[2 * (j + 0) + 1], a1);
        f = fmaxf(fmaf(sA[j + 1], v.y, sC[j + 1]), 0.f); a0 = fmaf(f, sW[2 * (j + 1)], a0); a1 = fmaf(f, sW[2 * (j + 1) + 1], a1);
        f = fmaxf(fmaf(sA[j + 2], v.z, sC[j + 2]), 0.f); a0 = fmaf(f, sW[2 * (j + 2)], a0); a1 = fmaf(f, sW[2 * (j + 2) + 1], a1);
        f = fmaxf(fmaf(sA[j + 3], v.w, sC[j + 3]), 0.f); a0 = fmaf(f, sW[2 * (j + 3)], a0); a1 = fmaf(f, sW[2 * (j + 3) + 1], a1);
    }
    out[2 * i]     = tanhf(a0);
    out[2 * i + 1] = tanhf(a1);
}

// ---------------- launch ----------------
extern "C" void kernel_launch(void* const* d_in, const int* in_sizes, int n_in,
                              void* d_out, int out_size) {
    const float* x    = (const float*)d_in[0];
    const int*   ei   = (const int*)d_in[1];
    const float* We   = (const float*)d_in[2];
    const float* be   = (const float*)d_in[3];
    const float* W1   = (const float*)d_in[4];
    const float* g1   = (const float*)d_in[6];
    const float* bt1  = (const float*)d_in[7];
    const float* W2   = (const float*)d_in[8];
    const float* g2   = (const float*)d_in[10];
    const float* bt2  = (const float*)d_in[11];
    const float* W3   = (const float*)d_in[12];
    const float* g3   = (const float*)d_in[14];
    const float* bt3  = (const float*)d_in[15];
    const float* Wf1  = (const float*)d_in[16];
    const float* gf   = (const float*)d_in[18];
    const float* btf  = (const float*)d_in[19];
    const float* Wf2  = (const float*)d_in[20];
    const float* bf2  = (const float*)d_in[21];
    float* out = (float*)d_out;
    // (b1/b2/b3/bf1 unused: uniform per-feature bias cancels inside BatchNorm)

    cudaFuncSetAttribute(k_mma_gemm, cudaFuncAttributeMaxDynamicSharedMemorySize, SMEM_MMA);
    cudaFuncSetAttribute(k_mma_head, cudaFuncAttributeMaxDynamicSharedMemorySize, SMEM_MMA);

    const int nb_scan = (N_NODES + 1023) / 1024;   // 98
    const int GB = 592;

    // graph preprocessing: degree -> dinv (fused), CSC build ; B-fragment prep
    k_zero_counts<<<(N_NODES + 255) / 256, 256>>>();
    k_count<<<(N_EDGES + 255) / 256, 256>>>(ei);
    k_scan_local<<<nb_scan, 1024>>>();
    k_scan_bsums<<<1, 128>>>(nb_scan);
    k_scan_add<<<nb_scan, 1024>>>();
    k_fill<<<(N_EDGES + 255) / 256, 256>>>(ei);
    k_prep_wfrag<<<52, 256>>>(W1, W2, W3, Wf1);

    // block 1: encoder fused; zeroes all BN bufs; h0 -> g ; stats -> buf0
    k_mma_gemm<<<N_TILES, 256, SMEM_MMA>>>(x, We, be, nullptr, nullptr, 0, 0, 0, 1, 0);
    k_aggregate<<<GB, 256>>>(0);

    // block 2: BN1 (buf0) fused; h0 -> h1 -> g ; stats -> buf1
    k_mma_gemm<<<N_TILES, 256, SMEM_MMA>>>(nullptr, nullptr, nullptr, g1, bt1, 1, 0, 1, 0, 0);
    k_aggregate<<<GB, 256>>>(1);

    // block 3: BN2 (buf1) fused; h1 -> h0 -> g ; stats -> buf2
    k_mma_gemm<<<N_TILES, 256, SMEM_MMA>>>(nullptr, nullptr, nullptr, g2, bt2, 2, 1, 0, 0, 1);
    k_aggregate<<<GB, 256>>>(2);

    // head: BN3 (buf2) fused; h2 in d_h0 -> ff (fp32 in d_g bytes) + stats -> buf3
    k_mma_head<<<N_TILES, 256, SMEM_MMA>>>(g3, bt3, 0, 2);
    k_out<<<(N_NODES + 127) / 128, 128>>>(gf, btf, Wf2, bf2, out);

    (void)in_sizes; (void)n_in; (void)out_size;
}

// round 15
// speedup vs baseline: 1.1943x; 1.0042x over previous
#include <cuda_runtime.h>
#include <cuda_fp16.h>
#include <math.h>
#include <stdint.h>

#define N_NODES 100000
#define N_EDGES 1600000
#define HID 128
#define EPS 1e-5f
#define N_TILES 782          // ceil(100000/128)
#define SM_STRIDE 136        // floats per staged row; 136 % 32 == 8 -> conflict-free frag LDS
#define SMEM_MMA (8 * 16 * SM_STRIDE * 4)   // 69632 B
#define NB_ZERO 391          // blocks zeroing counts in k_pre0
#define NB_WFRAG 52          // blocks building W fragments in k_pre0

// ---------------- scratch (device globals; referenced ONLY in device code) ----------------
__device__ float  d_h0[N_NODES * HID];
__device__ float  d_h1[N_NODES * HID];
__device__ __half d_g [N_NODES * HID];   // fp16 gather table; head reuses bytes as ff[N,32] fp32
__device__ float  d_agg[N_NODES * HID];  // fp32 aggregate stream (fp16 here compounds error -> fails gate)
__device__ float  d_dinv[N_NODES];
__device__ int    d_cnt[N_NODES];
__device__ int    d_cursor[N_NODES];
__device__ int    d_rowptr[N_NODES + 1];
__device__ int    d_col[N_EDGES];
__device__ int    d_bsums[128];
// 4 rotating BN stat buffers: 0,1,2 = blocks 1..3 (HID feats), 3 = head (32 feats)
__device__ double d_bnSum[4][HID];
__device__ double d_bnSqs[4][HID];
// B-fragment images: layers 0..2 at [(L*128 + kt*16 + nt)*32], head (Wf1) at [(384 + kt*4 + nt)*32]
__device__ uint4  d_Wfrag[(3 * 128 + 32) * 32];

// ---------------- helpers ----------------
__device__ __forceinline__ float* hbuf(int sel) { return sel == 0 ? d_h0 : d_h1; }

__device__ __forceinline__ uint32_t pack_bf16x2(float lo, float hi) {
    uint32_t d;
    asm("cvt.rn.bf16x2.f32 %0, %2, %1;" : "=r"(d) : "f"(lo), "f"(hi));
    return d;
}
__device__ __forceinline__ float bf_lo(uint32_t v) { return __uint_as_float(v << 16); }
__device__ __forceinline__ float bf_hi(uint32_t v) { return __uint_as_float(v & 0xffff0000u); }

__device__ __forceinline__ void split2(float a, float b, uint32_t& hi, uint32_t& lo) {
    hi = pack_bf16x2(a, b);
    lo = pack_bf16x2(a - bf_lo(hi), b - bf_hi(hi));
}

__device__ __forceinline__ void mma_bf16(float c[4], uint32_t a0, uint32_t a1,
                                         uint32_t a2, uint32_t a3,
                                         uint32_t b0, uint32_t b1) {
    asm volatile(
        "mma.sync.aligned.m16n8k16.row.col.f32.bf16.bf16.f32 "
        "{%0,%1,%2,%3}, {%4,%5,%6,%7}, {%8,%9}, {%0,%1,%2,%3};"
        : "+f"(c[0]), "+f"(c[1]), "+f"(c[2]), "+f"(c[3])
        : "r"(a0), "r"(a1), "r"(a2), "r"(a3), "r"(b0), "r"(b1));
}

__device__ __forceinline__ void addh4(float4& a, uint2 v) {
    float2 f0 = __half22float2(*reinterpret_cast<const __half2*>(&v.x));
    float2 f1 = __half22float2(*reinterpret_cast<const __half2*>(&v.y));
    a.x += f0.x; a.y += f0.y; a.z += f1.x; a.w += f1.y;
}

// per-lane BN coefficients for features 4*lane..4*lane+3 from stat buffer rd
__device__ __forceinline__ void bn_coeffs4(int rd, int lane,
                                           const float* __restrict__ gamma,
                                           const float* __restrict__ beta,
                                           float4& A, float4& C) {
    const float invn = 1.0f / (float)N_NODES;
    float4 gm = __ldg(&((const float4*)gamma)[lane]);
    float4 bt = __ldg(&((const float4*)beta)[lane]);
    int f = 4 * lane;
    float m, v;
    m = (float)d_bnSum[rd][f + 0] * invn; v = (float)d_bnSqs[rd][f + 0] * invn - m * m;
    A.x = gm.x * rsqrtf(v + EPS); C.x = bt.x - m * A.x;
    m = (float)d_bnSum[rd][f + 1] * invn; v = (float)d_bnSqs[rd][f + 1] * invn - m * m;
    A.y = gm.y * rsqrtf(v + EPS); C.y = bt.y - m * A.y;
    m = (float)d_bnSum[rd][f + 2] * invn; v = (float)d_bnSqs[rd][f + 2] * invn - m * m;
    A.z = gm.z * rsqrtf(v + EPS); C.z = bt.z - m * A.z;
    m = (float)d_bnSum[rd][f + 3] * invn; v = (float)d_bnSqs[rd][f + 3] * invn - m * m;
    A.w = gm.w * rsqrtf(v + EPS); C.w = bt.w - m * A.w;
}

// ---------------- pre0: zero counts/cursor (blocks 0..390) + W fragment prep (391..442) --
__global__ void k_pre0(const float* __restrict__ W1,
                       const float* __restrict__ W2,
                       const float* __restrict__ W3,
                       const float* __restrict__ Wf1) {
    int b = blockIdx.x;
    if (b < NB_ZERO) {
        int i = b * 256 + threadIdx.x;
        if (i < N_NODES) { d_cnt[i] = 0; d_cursor[i] = 0; }
    } else {
        int idx = (b - NB_ZERO) * 256 + threadIdx.x;
        if (idx >= 3 * 4096 + 1024) return;
        if (idx < 3 * 4096) {
            int lane = idx & 31;
            int nt = (idx >> 5) & 15;
            int kt = (idx >> 9) & 7;
            int L  = idx >> 12;
            const float* W = (L == 0) ? W1 : (L == 1) ? W2 : W3;
            int g = lane >> 2, t = lane & 3;
            int n = nt * 8 + g;
            int k0 = kt * 16 + 2 * t;
            int k1 = k0 + 8;
            uint32_t h0, l0, h1, l1;
            split2(W[k0 * 128 + n], W[(k0 + 1) * 128 + n], h0, l0);
            split2(W[k1 * 128 + n], W[(k1 + 1) * 128 + n], h1, l1);
            uint4 v; v.x = h0; v.y = h1; v.z = l0; v.w = l1;
            d_Wfrag[(L * 128 + kt * 16 + nt) * 32 + lane] = v;
        } else {
            int r = idx - 3 * 4096;
            int lane = r & 31;
            int nt = (r >> 5) & 3;
            int kt = (r >> 7) & 7;
            int g = lane >> 2, t = lane & 3;
            int n = nt * 8 + g;
            int k0 = kt * 16 + 2 * t;
            int k1 = k0 + 8;
            uint32_t h0, l0, h1, l1;
            split2(Wf1[k0 * 32 + n], Wf1[(k0 + 1) * 32 + n], h0, l0);
            split2(Wf1[k1 * 32 + n], Wf1[(k1 + 1) * 32 + n], h1, l1);
            uint4 v; v.x = h0; v.y = h1; v.z = l0; v.w = l1;
            d_Wfrag[(384 + kt * 4 + nt) * 32 + lane] = v;
        }
    }
}

__global__ void k_count(const int* __restrict__ ei) {
    int e = blockIdx.x * blockDim.x + threadIdx.x;
    if (e < N_EDGES) atomicAdd(&d_cnt[ei[N_EDGES + e]], 1);
}
__global__ void k_scan_local() {
    __shared__ int s[1024];
    int tid = threadIdx.x;
    int idx = blockIdx.x * 1024 + tid;
    int v = (idx < N_NODES) ? d_cnt[idx] : 0;
    if (idx < N_NODES) d_dinv[idx] = rsqrtf((float)v + 1.0f);   // fused dinv
    s[tid] = v;
    __syncthreads();
    for (int off = 1; off < 1024; off <<= 1) {
        int t = (tid >= off) ? s[tid - off] : 0;
        __syncthreads();
        s[tid] += t;
        __syncthreads();
    }
    if (idx < N_NODES) d_rowptr[idx] = s[tid] - v;   // exclusive
    if (tid == 1023) d_bsums[blockIdx.x] = s[1023];
}
// scan_add with inlined bsums prefix (every block recomputes the 128-wide scan)
__global__ void k_scan_add(int nb) {
    __shared__ int sb[128];
    int t = threadIdx.x;
    if (t < 128) sb[t] = (t < nb) ? d_bsums[t] : 0;
    __syncthreads();
    #pragma unroll
    for (int off = 1; off < 128; off <<= 1) {
        int v = (t < 128 && t >= off) ? sb[t - off] : 0;
        __syncthreads();
        if (t < 128) sb[t] += v;
        __syncthreads();
    }
    int idx = blockIdx.x * 1024 + t;
    int off = (blockIdx.x > 0) ? sb[blockIdx.x - 1] : 0;
    if (idx < N_NODES) d_rowptr[idx] += off;
    if (blockIdx.x == 0 && t == 0) d_rowptr[N_NODES] = sb[nb - 1];
}
__global__ void k_fill(const int* __restrict__ ei) {
    int e = blockIdx.x * blockDim.x + threadIdx.x;
    if (e < N_EDGES) {
        int s = ei[e];
        int d = ei[N_EDGES + e];
        int pos = d_rowptr[d] + atomicAdd(&d_cursor[d], 1);
        d_col[pos] = s;
    }
}

// ---------------- tensor GEMM: d_g(fp16) = dinv * (h_new @ W_layer) ----------------
// first=1: h_new = relu(x@We+be) (encoder); also zeroes all 4 BN stat buffers (CTA 0).
// first=0: h_new = relu(bnA*agg + bnC) + h_old, coeffs computed inline from buf bn_rd.
__global__ void __launch_bounds__(256, 2) k_mma_gemm(
    const float* __restrict__ x, const float* __restrict__ We,
    const float* __restrict__ be,
    const float* __restrict__ gamma, const float* __restrict__ beta,
    int layer, int hin_sel, int hout_sel, int first, int bn_rd) {
    extern __shared__ float smf[];
    const int lane = threadIdx.x & 31;
    const int wid = threadIdx.x >> 5;
    const int tile = blockIdx.x;
    float* sw = smf + wid * 16 * SM_STRIDE;
    const int rbase = tile * 128 + wid * 16;

    if (first && blockIdx.x == 0 && threadIdx.x < HID) {
        #pragma unroll
        for (int r = 0; r < 4; r++) {
            d_bnSum[r][threadIdx.x] = 0.0;
            d_bnSqs[r][threadIdx.x] = 0.0;
        }
    }

    // ---- phase 1: h_new for this warp's 16 rows ----
    if (first) {
        float4 w0 = __ldg(&((const float4*)We)[lane]);
        float4 w1 = __ldg(&((const float4*)We)[32 + lane]);
        float4 b  = __ldg(&((const float4*)be)[lane]);
        float4* H04 = reinterpret_cast<float4*>(d_h0);
        #pragma unroll 4
        for (int r = 0; r < 16; r++) {
            int row = rbase + r;
            int rs = (row < N_NODES) ? row : N_NODES - 1;
            float x0 = __ldg(&x[2 * rs]), x1 = __ldg(&x[2 * rs + 1]);
            float4 h;
            h.x = fmaxf(fmaf(x0, w0.x, fmaf(x1, w1.x, b.x)), 0.f);
            h.y = fmaxf(fmaf(x0, w0.y, fmaf(x1, w1.y, b.y)), 0.f);
            h.z = fmaxf(fmaf(x0, w0.z, fmaf(x1, w1.z, b.z)), 0.f);
            h.w = fmaxf(fmaf(x0, w0.w, fmaf(x1, w1.w, b.w)), 0.f);
            if (row < N_NODES) H04[(size_t)row * 32 + lane] = h;
            *reinterpret_cast<float4*>(sw + r * SM_STRIDE + 4 * lane) = h;
        }
    } else {
        float4 ba, bc;
        bn_coeffs4(bn_rd, lane, gamma, beta, ba, bc);
        const float4* A4 = reinterpret_cast<const float4*>(d_agg);
        const float4* HI4 = reinterpret_cast<const float4*>(hbuf(hin_sel));
        float4* HO4 = reinterpret_cast<float4*>(hbuf(hout_sel));
        #pragma unroll 4
        for (int r = 0; r < 16; r++) {
            int row = rbase + r;
            int rs = (row < N_NODES) ? row : N_NODES - 1;
            float4 v = A4[(size_t)rs * 32 + lane];
            float4 ho = HI4[(size_t)rs * 32 + lane];
            float4 h;
            h.x = fmaxf(fmaf(ba.x, v.x, bc.x), 0.f) + ho.x;
            h.y = fmaxf(fmaf(ba.y, v.y, bc.y), 0.f) + ho.y;
            h.z = fmaxf(fmaf(ba.z, v.z, bc.z), 0.f) + ho.z;
            h.w = fmaxf(fmaf(ba.w, v.w, bc.w), 0.f) + ho.w;
            if (row < N_NODES) HO4[(size_t)row * 32 + lane] = h;
            *reinterpret_cast<float4*>(sw + r * SM_STRIDE + 4 * lane) = h;
        }
    }
    __syncwarp();

    // ---- phase 2: A fragments (split bf16), 8 k-tiles ----
    const int g = lane >> 2, t = lane & 3;
    const float* r0p = sw + g * SM_STRIDE;
    const float* r1p = sw + (g + 8) * SM_STRIDE;
    uint32_t ah[32], al[32];
    #pragma unroll
    for (int kt = 0; kt < 8; kt++) {
        float2 p0 = *reinterpret_cast<const float2*>(r0p + 16 * kt + 2 * t);
        float2 p1 = *reinterpret_cast<const float2*>(r1p + 16 * kt + 2 * t);
        float2 p2 = *reinterpret_cast<const float2*>(r0p + 16 * kt + 2 * t + 8);
        float2 p3 = *reinterpret_cast<const float2*>(r1p + 16 * kt + 2 * t + 8);
        split2(p0.x, p0.y, ah[4 * kt + 0], al[4 * kt + 0]);
        split2(p1.x, p1.y, ah[4 * kt + 1], al[4 * kt + 1]);
        split2(p2.x, p2.y, ah[4 * kt + 2], al[4 * kt + 2]);
        split2(p3.x, p3.y, ah[4 * kt + 3], al[4 * kt + 3]);
    }

    // ---- phase 3: mma over 16 n-tiles (2 at a time), 3-pass split bf16; fp16 epilogue ----
    const uint4* Wf = &d_Wfrag[layer * 128 * 32];
    int row0 = rbase + g, row1 = rbase + g + 8;
    float dv0 = d_dinv[(row0 < N_NODES) ? row0 : 0];
    float dv1 = d_dinv[(row1 < N_NODES) ? row1 : 0];

    #pragma unroll
    for (int ntp = 0; ntp < 8; ntp++) {
        float c0[4] = {0.f, 0.f, 0.f, 0.f};
        float c1[4] = {0.f, 0.f, 0.f, 0.f};
        #pragma unroll
        for (int kt = 0; kt < 8; kt++) {
            uint4 B0 = __ldg(&Wf[(kt * 16 + 2 * ntp) * 32 + lane]);
            uint4 B1 = __ldg(&Wf[(kt * 16 + 2 * ntp + 1) * 32 + lane]);
            uint32_t a0 = ah[4 * kt], a1 = ah[4 * kt + 1], a2 = ah[4 * kt + 2], a3 = ah[4 * kt + 3];
            uint32_t l0 = al[4 * kt], l1 = al[4 * kt + 1], l2 = al[4 * kt + 2], l3 = al[4 * kt + 3];
            mma_bf16(c0, a0, a1, a2, a3, B0.x, B0.y);   // Ah * Bh
            mma_bf16(c0, l0, l1, l2, l3, B0.x, B0.y);   // Al * Bh
            mma_bf16(c0, a0, a1, a2, a3, B0.z, B0.w);   // Ah * Bl
            mma_bf16(c1, a0, a1, a2, a3, B1.x, B1.y);
            mma_bf16(c1, l0, l1, l2, l3, B1.x, B1.y);
            mma_bf16(c1, a0, a1, a2, a3, B1.z, B1.w);
        }
        int col0 = (2 * ntp) * 8 + 2 * t;
        int col1 = (2 * ntp + 1) * 8 + 2 * t;
        if (row0 < N_NODES) {
            *reinterpret_cast<__half2*>(d_g + (size_t)row0 * 128 + col0) =
                __floats2half2_rn(c0[0] * dv0, c0[1] * dv0);
            *reinterpret_cast<__half2*>(d_g + (size_t)row0 * 128 + col1) =
                __floats2half2_rn(c1[0] * dv0, c1[1] * dv0);
        }
        if (row1 < N_NODES) {
            *reinterpret_cast<__half2*>(d_g + (size_t)row1 * 128 + col0) =
                __floats2half2_rn(c0[2] * dv1, c0[3] * dv1);
            *reinterpret_cast<__half2*>(d_g + (size_t)row1 * 128 + col1) =
                __floats2half2_rn(c1[2] * dv1, c1[3] * dv1);
        }
    }
}

// ---------------- aggregation: agg[i] = dinv[i]*(sum_in g[src] + g[i]); BN partials ---
__global__ void k_aggregate(int bw) {
    __shared__ float sS[HID];
    __shared__ float sQ[HID];
    if (threadIdx.x < HID) { sS[threadIdx.x] = 0.f; sQ[threadIdx.x] = 0.f; }
    __syncthreads();

    const int lane = threadIdx.x & 31;
    const int gwid = (blockIdx.x * blockDim.x + threadIdx.x) >> 5;
    const int nwarps = (gridDim.x * blockDim.x) >> 5;
    const uint2* g2 = reinterpret_cast<const uint2*>(d_g);
    float4* agg4 = reinterpret_cast<float4*>(d_agg);

    float4 lsum = make_float4(0.f, 0.f, 0.f, 0.f);
    float4 lsq  = make_float4(0.f, 0.f, 0.f, 0.f);

    for (int i = gwid; i < N_NODES; i += nwarps) {
        float4 acc = make_float4(0.f, 0.f, 0.f, 0.f);
        addh4(acc, __ldg(&g2[(size_t)i * 32 + lane]));   // self loop
        int e0 = d_rowptr[i], e1 = d_rowptr[i + 1];
        int e = e0;
        for (; e + 4 <= e1; e += 4) {
            int s0 = __ldg(&d_col[e]);
            int s1 = __ldg(&d_col[e + 1]);
            int s2 = __ldg(&d_col[e + 2]);
            int s3 = __ldg(&d_col[e + 3]);
            uint2 v0 = __ldg(&g2[(size_t)s0 * 32 + lane]);
            uint2 v1 = __ldg(&g2[(size_t)s1 * 32 + lane]);
            uint2 v2 = __ldg(&g2[(size_t)s2 * 32 + lane]);
            uint2 v3 = __ldg(&g2[(size_t)s3 * 32 + lane]);
            addh4(acc, v0); addh4(acc, v1); addh4(acc, v2); addh4(acc, v3);
        }
        for (; e < e1; e++) {
            int s0 = __ldg(&d_col[e]);
            addh4(acc, __ldg(&g2[(size_t)s0 * 32 + lane]));
        }
        float dv = d_dinv[i];
        acc.x *= dv; acc.y *= dv; acc.z *= dv; acc.w *= dv;
        __stcs(&agg4[(size_t)i * 32 + lane], acc);       // streaming store, no reuse
        lsum.x += acc.x; lsum.y += acc.y; lsum.z += acc.z; lsum.w += acc.w;
        lsq.x = fmaf(acc.x, acc.x, lsq.x);
        lsq.y = fmaf(acc.y, acc.y, lsq.y);
        lsq.z = fmaf(acc.z, acc.z, lsq.z);
        lsq.w = fmaf(acc.w, acc.w, lsq.w);
    }
    int f = 4 * lane;
    atomicAdd(&sS[f + 0], lsum.x); atomicAdd(&sS[f + 1], lsum.y);
    atomicAdd(&sS[f + 2], lsum.z); atomicAdd(&sS[f + 3], lsum.w);
    atomicAdd(&sQ[f + 0], lsq.x);  atomicAdd(&sQ[f + 1], lsq.y);
    atomicAdd(&sQ[f + 2], lsq.z);  atomicAdd(&sQ[f + 3], lsq.w);
    __syncthreads();
    if (threadIdx.x < HID) {
        atomicAdd(&d_bnSum[bw][threadIdx.x], (double)sS[threadIdx.x]);
        atomicAdd(&d_bnSqs[bw][threadIdx.x], (double)sQ[threadIdx.x]);
    }
}

// ---------------- head: h3 = BN3(agg)+h2 (smem only); ff = h3@Wf1 via mma; stats->buf3 --
__global__ void __launch_bounds__(256, 2) k_mma_head(
    const float* __restrict__ gamma, const float* __restrict__ beta,
    int hin_sel, int bn_rd) {
    extern __shared__ float smf[];
    __shared__ float sS[32];
    __shared__ float sQ[32];
    const int lane = threadIdx.x & 31;
    const int wid = threadIdx.x >> 5;
    const int tile = blockIdx.x;
    float* sw = smf + wid * 16 * SM_STRIDE;
    const int rbase = tile * 128 + wid * 16;

    if (threadIdx.x < 32) { sS[threadIdx.x] = 0.f; sQ[threadIdx.x] = 0.f; }
    __syncthreads();

    // ---- phase 1: h3 rows into smem (no gmem store) ----
    {
        float4 ba, bc;
        bn_coeffs4(bn_rd, lane, gamma, beta, ba, bc);
        const float4* A4 = reinterpret_cast<const float4*>(d_agg);
        const float4* HI4 = reinterpret_cast<const float4*>(hbuf(hin_sel));
        #pragma unroll 4
        for (int r = 0; r < 16; r++) {
            int row = rbase + r;
            int rs = (row < N_NODES) ? row : N_NODES - 1;
            float4 v = A4[(size_t)rs * 32 + lane];
            float4 ho = HI4[(size_t)rs * 32 + lane];
            float4 h;
            h.x = fmaxf(fmaf(ba.x, v.x, bc.x), 0.f) + ho.x;
            h.y = fmaxf(fmaf(ba.y, v.y, bc.y), 0.f) + ho.y;
            h.z = fmaxf(fmaf(ba.z, v.z, bc.z), 0.f) + ho.z;
            h.w = fmaxf(fmaf(ba.w, v.w, bc.w), 0.f) + ho.w;
            *reinterpret_cast<float4*>(sw + r * SM_STRIDE + 4 * lane) = h;
        }
    }
    __syncwarp();

    // ---- phase 2: A fragments ----
    const int g = lane >> 2, t = lane & 3;
    const float* r0p = sw + g * SM_STRIDE;
    const float* r1p = sw + (g + 8) * SM_STRIDE;
    uint32_t ah[32], al[32];
    #pragma unroll
    for (int kt = 0; kt < 8; kt++) {
        float2 p0 = *reinterpret_cast<const float2*>(r0p + 16 * kt + 2 * t);
        float2 p1 = *reinterpret_cast<const float2*>(r1p + 16 * kt + 2 * t);
        float2 p2 = *reinterpret_cast<const float2*>(r0p + 16 * kt + 2 * t + 8);
        float2 p3 = *reinterpret_cast<const float2*>(r1p + 16 * kt + 2 * t + 8);
        split2(p0.x, p0.y, ah[4 * kt + 0], al[4 * kt + 0]);
        split2(p1.x, p1.y, ah[4 * kt + 1], al[4 * kt + 1]);
        split2(p2.x, p2.y, ah[4 * kt + 2], al[4 * kt + 2]);
        split2(p3.x, p3.y, ah[4 * kt + 3], al[4 * kt + 3]);
    }

    // ---- phase 3: N=32 -> 2 ntp iterations; ff fp32 into d_g bytes; local stats ----
    const uint4* Wf = &d_Wfrag[384 * 32];
    float* ff = reinterpret_cast<float*>(d_g);
    int row0 = rbase + g, row1 = rbase + g + 8;
    bool v0 = row0 < N_NODES, v1 = row1 < N_NODES;
    float sl[8] = {0, 0, 0, 0, 0, 0, 0, 0};
    float ql[8] = {0, 0, 0, 0, 0, 0, 0, 0};

    #pragma unroll
    for (int ntp = 0; ntp < 2; ntp++) {
        float c0[4] = {0.f, 0.f, 0.f, 0.f};
        float c1[4] = {0.f, 0.f, 0.f, 0.f};
        #pragma unroll
        for (int kt = 0; kt < 8; kt++) {
            uint4 B0 = __ldg(&Wf[(kt * 4 + 2 * ntp) * 32 + lane]);
            uint4 B1 = __ldg(&Wf[(kt * 4 + 2 * ntp + 1) * 32 + lane]);
            uint32_t a0 = ah[4 * kt], a1 = ah[4 * kt + 1], a2 = ah[4 * kt + 2], a3 = ah[4 * kt + 3];
            uint32_t l0 = al[4 * kt], l1 = al[4 * kt + 1], l2 = al[4 * kt + 2], l3 = al[4 * kt + 3];
            mma_bf16(c0, a0, a1, a2, a3, B0.x, B0.y);
            mma_bf16(c0, l0, l1, l2, l3, B0.x, B0.y);
            mma_bf16(c0, a0, a1, a2, a3, B0.z, B0.w);
            mma_bf16(c1, a0, a1, a2, a3, B1.x, B1.y);
            mma_bf16(c1, l0, l1, l2, l3, B1.x, B1.y);
            mma_bf16(c1, a0, a1, a2, a3, B1.z, B1.w);
        }
        int col0 = (2 * ntp) * 8 + 2 * t;
        int col1 = col0 + 8;
        if (v0) {
            *reinterpret_cast<float2*>(ff + (size_t)row0 * 32 + col0) = make_float2(c0[0], c0[1]);
            *reinterpret_cast<float2*>(ff + (size_t)row0 * 32 + col1) = make_float2(c1[0], c1[1]);
            sl[4 * ntp + 0] += c0[0]; ql[4 * ntp + 0] += c0[0] * c0[0];
            sl[4 * ntp + 1] += c0[1]; ql[4 * ntp + 1] += c0[1] * c0[1];
            sl[4 * ntp + 2] += c1[0]; ql[4 * ntp + 2] += c1[0] * c1[0];
            sl[4 * ntp + 3] += c1[1]; ql[4 * ntp + 3] += c1[1] * c1[1];
        }
        if (v1) {
            *reinterpret_cast<float2*>(ff + (size_t)row1 * 32 + col0) = make_float2(c0[2], c0[3]);
            *reinterpret_cast<float2*>(ff + (size_t)row1 * 32 + col1) = make_float2(c1[2], c1[3]);
            sl[4 * ntp + 0] += c0[2]; ql[4 * ntp + 0] += c0[2] * c0[2];
            sl[4 * ntp + 1] += c0[3]; ql[4 * ntp + 1] += c0[3] * c0[3];
            sl[4 * ntp + 2] += c1[2]; ql[4 * ntp + 2] += c1[2] * c1[2];
            sl[4 * ntp + 3] += c1[3]; ql[4 * ntp + 3] += c1[3] * c1[3];
        }
    }

    // reduce over g (lanes xor 4,8,16), then lanes 0..3 (t==lane) hold totals
    #pragma unroll
    for (int off = 4; off < 32; off <<= 1) {
        #pragma unroll
        for (int j = 0; j < 8; j++) {
            sl[j] += __shfl_xor_sync(0xffffffffu, sl[j], off);
            ql[j] += __shfl_xor_sync(0xffffffffu, ql[j], off);
        }
    }
    if (lane < 4) {
        #pragma unroll
        for (int j = 0; j < 8; j++) {
            // j = 4*ntp + k : feature = 16*ntp + 8*(k>>1) + 2*lane + (k&1)
            int ntp = j >> 2, k = j & 3;
            int feat = 16 * ntp + 8 * (k >> 1) + 2 * lane + (k & 1);
            atomicAdd(&sS[feat], sl[j]);
            atomicAdd(&sQ[feat], ql[j]);
        }
    }
    __syncthreads();
    if (threadIdx.x < 32) {
        atomicAdd(&d_bnSum[3][threadIdx.x], (double)sS[threadIdx.x]);
        atomicAdd(&d_bnSqs[3][threadIdx.x], (double)sQ[threadIdx.x]);
    }
}

// ---------------- out = tanh(relu(a*ff+c) @ Wf2 + bf2), BN coeffs inline from buf3 ------
__global__ void k_out(const float* __restrict__ gf, const float* __restrict__ btf,
                      const float* __restrict__ Wf2,
                      const float* __restrict__ bf2,
                      float* __restrict__ out) {
    __shared__ float sA[32], sC[32], sW[64], sB[2];
    int t = threadIdx.x;
    if (t < 32) {
        const float invn = 1.0f / (float)N_NODES;
        float m = (float)d_bnSum[3][t] * invn;
        float v = (float)d_bnSqs[3][t] * invn - m * m;
        float a = __ldg(&gf[t]) * rsqrtf(v + EPS);
        sA[t] = a;
        sC[t] = __ldg(&btf[t]) - m * a;
    }
    if (t < 64) sW[t] = Wf2[t];
    if (t < 2) sB[t] = bf2[t];
    __syncthreads();
    int i = blockIdx.x * blockDim.x + t;
    if (i >= N_NODES) return;
    float a0 = sB[0], a1 = sB[1];
    const float4* f4 = reinterpret_cast<const float4*>(reinterpret_cast<const float*>(d_g) + (size_t)i * 32);
    #pragma unroll
    for (int j4 = 0; j4 < 8; j4++) {
        float4 v = f4[j4];
        int j = j4 * 4;
        float f;
        f = fmaxf(fmaf(sA[j + 0], v.x, sC[j + 0]), 0.f); a0 = fmaf(f, sW[2 * (j + 0)], a0); a1 = fmaf(f, sW[2 * (j + 0) + 1], a1);
        f = fmaxf(fmaf(sA[j + 1], v.y, sC[j + 1]), 0.f); a0 = fmaf(f, sW[2 * (j + 1)], a0); a1 = fmaf(f, sW[2 * (j + 1) + 1], a1);
        f = fmaxf(fmaf(sA[j + 2], v.z, sC[j + 2]), 0.f); a0 = fmaf(f, sW[2 * (j + 2)], a0); a1 = fmaf(f, sW[2 * (j + 2) + 1], a1);
        f = fmaxf(fmaf(sA[j + 3], v.w, sC[j + 3]), 0.f); a0 = fmaf(f, sW[2 * (j + 3)], a0); a1 = fmaf(f, sW[2 * (j + 3) + 1], a1);
    }
    out[2 * i]     = tanhf(a0);
    out[2 * i + 1] = tanhf(a1);
}

// ---------------- launch ----------------
extern "C" void kernel_launch(void* const* d_in, const int* in_sizes, int n_in,
                              void* d_out, int out_size) {
    const float* x    = (const float*)d_in[0];
    const int*   ei   = (const int*)d_in[1];
    const float* We   = (const float*)d_in[2];
    const float* be   = (const float*)d_in[3];
    const float* W1   = (const float*)d_in[4];
    const float* g1   = (const float*)d_in[6];
    const float* bt1  = (const float*)d_in[7];
    const float* W2   = (const float*)d_in[8];
    const float* g2   = (const float*)d_in[10];
    const float* bt2  = (const float*)d_in[11];
    const float* W3   = (const float*)d_in[12];
    const float* g3   = (const float*)d_in[14];
    const float* bt3  = (const float*)d_in[15];
    const float* Wf1  = (const float*)d_in[16];
    const float* gf   = (const float*)d_in[18];
    const float* btf  = (const float*)d_in[19];
    const float* Wf2  = (const float*)d_in[20];
    const float* bf2  = (const float*)d_in[21];
    float* out = (float*)d_out;
    // (b1/b2/b3/bf1 unused: uniform per-feature bias cancels inside BatchNorm)

    cudaFuncSetAttribute(k_mma_gemm, cudaFuncAttributeMaxDynamicSharedMemorySize, SMEM_MMA);
    cudaFuncSetAttribute(k_mma_head, cudaFuncAttributeMaxDynamicSharedMemorySize, SMEM_MMA);

    const int nb_scan = (N_NODES + 1023) / 1024;   // 98
    const int GB = 592;

    // graph preprocessing: zero+wfrag fused; count; scan (dinv fused); add (bsums inlined); fill
    k_pre0<<<NB_ZERO + NB_WFRAG, 256>>>(W1, W2, W3, Wf1);
    k_count<<<(N_EDGES + 255) / 256, 256>>>(ei);
    k_scan_local<<<nb_scan, 1024>>>();
    k_scan_add<<<nb_scan, 1024>>>(nb_scan);
    k_fill<<<(N_EDGES + 255) / 256, 256>>>(ei);

    // block 1: encoder fused; zeroes all BN bufs; h0 -> g ; stats -> buf0
    k_mma_gemm<<<N_TILES, 256, SMEM_MMA>>>(x, We, be, nullptr, nullptr, 0, 0, 0, 1, 0);
    k_aggregate<<<GB, 256>>>(0);

    // block 2: BN1 (buf0) fused; h0 -> h1 -> g ; stats -> buf1
    k_mma_gemm<<<N_TILES, 256, SMEM_MMA>>>(nullptr, nullptr, nullptr, g1, bt1, 1, 0, 1, 0, 0);
    k_aggregate<<<GB, 256>>>(1);

    // block 3: BN2 (buf1) fused; h1 -> h0 -> g ; stats -> buf2
    k_mma_gemm<<<N_TILES, 256, SMEM_MMA>>>(nullptr, nullptr, nullptr, g2, bt2, 2, 1, 0, 0, 1);
    k_aggregate<<<GB, 256>>>(2);

    // head: BN3 (buf2) fused; h2 in d_h0 -> ff (fp32 in d_g bytes) + stats -> buf3
    k_mma_head<<<N_TILES, 256, SMEM_MMA>>>(g3, bt3, 0, 2);
    k_out<<<(N_NODES + 127) / 128, 128>>>(gf, btf, Wf2, bf2, out);

    (void)in_sizes; (void)n_in; (void)out_size;
}

// round 16
// speedup vs baseline: 1.2235x; 1.0244x over previous
#include <cuda_runtime.h>
#include <cuda_fp16.h>
#include <math.h>
#include <stdint.h>

#define N_NODES 100000
#define N_EDGES 1600000
#define HID 128
#define EPS 1e-5f
#define N_TILES 782          // ceil(100000/128)
#define SM_STRIDE 136        // floats per staged row; 136 % 32 == 8 -> conflict-free frag LDS
#define SMEM_MMA (8 * 16 * SM_STRIDE * 4)   // 69632 B
#define NB_ZERO 391          // blocks zeroing counts in k_pre0
#define NB_WFRAG 52          // blocks building W fragments in k_pre0

// ---------------- scratch (device globals; referenced ONLY in device code) ----------------
__device__ float  d_h0[N_NODES * HID];
__device__ float  d_h1[N_NODES * HID];
__device__ __half d_g [N_NODES * HID];   // fp16 gather table; head reuses bytes as ff[N,32] fp32
__device__ float  d_agg[N_NODES * HID];  // fp32 aggregate stream (fp16 here compounds error -> fails gate)
__device__ float  d_dinv[N_NODES];
__device__ int    d_cnt[N_NODES];
__device__ int    d_cursor[N_NODES];
__device__ int    d_rowptr[N_NODES + 1];
__device__ int    d_col[N_EDGES];
__device__ int    d_bsums[128];
// 4 rotating BN stat buffers: 0,1,2 = blocks 1..3 (HID feats), 3 = head (32 feats)
__device__ double d_bnSum[4][HID];
__device__ double d_bnSqs[4][HID];
// B-fragment images: layers 0..2 at [(L*128 + kt*16 + nt)*32], head (Wf1) at [(384 + kt*4 + nt)*32]
__device__ uint4  d_Wfrag[(3 * 128 + 32) * 32];

// ---------------- helpers ----------------
__device__ __forceinline__ float* hbuf(int sel) { return sel == 0 ? d_h0 : d_h1; }

__device__ __forceinline__ uint32_t pack_bf16x2(float lo, float hi) {
    uint32_t d;
    asm("cvt.rn.bf16x2.f32 %0, %2, %1;" : "=r"(d) : "f"(lo), "f"(hi));
    return d;
}
__device__ __forceinline__ float bf_lo(uint32_t v) { return __uint_as_float(v << 16); }
__device__ __forceinline__ float bf_hi(uint32_t v) { return __uint_as_float(v & 0xffff0000u); }

__device__ __forceinline__ void split2(float a, float b, uint32_t& hi, uint32_t& lo) {
    hi = pack_bf16x2(a, b);
    lo = pack_bf16x2(a - bf_lo(hi), b - bf_hi(hi));
}

__device__ __forceinline__ void mma_bf16(float c[4], uint32_t a0, uint32_t a1,
                                         uint32_t a2, uint32_t a3,
                                         uint32_t b0, uint32_t b1) {
    asm volatile(
        "mma.sync.aligned.m16n8k16.row.col.f32.bf16.bf16.f32 "
        "{%0,%1,%2,%3}, {%4,%5,%6,%7}, {%8,%9}, {%0,%1,%2,%3};"
        : "+f"(c[0]), "+f"(c[1]), "+f"(c[2]), "+f"(c[3])
        : "r"(a0), "r"(a1), "r"(a2), "r"(a3), "r"(b0), "r"(b1));
}

__device__ __forceinline__ void addh4(float4& a, uint2 v) {
    float2 f0 = __half22float2(*reinterpret_cast<const __half2*>(&v.x));
    float2 f1 = __half22float2(*reinterpret_cast<const __half2*>(&v.y));
    a.x += f0.x; a.y += f0.y; a.z += f1.x; a.w += f1.y;
}

// per-lane BN coefficients for features 4*lane..4*lane+3 from stat buffer rd
__device__ __forceinline__ void bn_coeffs4(int rd, int lane,
                                           const float* __restrict__ gamma,
                                           const float* __restrict__ beta,
                                           float4& A, float4& C) {
    const float invn = 1.0f / (float)N_NODES;
    float4 gm = __ldg(&((const float4*)gamma)[lane]);
    float4 bt = __ldg(&((const float4*)beta)[lane]);
    int f = 4 * lane;
    float m, v;
    m = (float)d_bnSum[rd][f + 0] * invn; v = (float)d_bnSqs[rd][f + 0] * invn - m * m;
    A.x = gm.x * rsqrtf(v + EPS); C.x = bt.x - m * A.x;
    m = (float)d_bnSum[rd][f + 1] * invn; v = (float)d_bnSqs[rd][f + 1] * invn - m * m;
    A.y = gm.y * rsqrtf(v + EPS); C.y = bt.y - m * A.y;
    m = (float)d_bnSum[rd][f + 2] * invn; v = (float)d_bnSqs[rd][f + 2] * invn - m * m;
    A.z = gm.z * rsqrtf(v + EPS); C.z = bt.z - m * A.z;
    m = (float)d_bnSum[rd][f + 3] * invn; v = (float)d_bnSqs[rd][f + 3] * invn - m * m;
    A.w = gm.w * rsqrtf(v + EPS); C.w = bt.w - m * A.w;
}

// ---------------- pre0: zero counts/cursor (blocks 0..390) + W fragment prep (391..442) --
__global__ void k_pre0(const float* __restrict__ W1,
                       const float* __restrict__ W2,
                       const float* __restrict__ W3,
                       const float* __restrict__ Wf1) {
    int b = blockIdx.x;
    if (b < NB_ZERO) {
        int i = b * 256 + threadIdx.x;
        if (i < N_NODES) { d_cnt[i] = 0; d_cursor[i] = 0; }
    } else {
        int idx = (b - NB_ZERO) * 256 + threadIdx.x;
        if (idx >= 3 * 4096 + 1024) return;
        if (idx < 3 * 4096) {
            int lane = idx & 31;
            int nt = (idx >> 5) & 15;
            int kt = (idx >> 9) & 7;
            int L  = idx >> 12;
            const float* W = (L == 0) ? W1 : (L == 1) ? W2 : W3;
            int g = lane >> 2, t = lane & 3;
            int n = nt * 8 + g;
            int k0 = kt * 16 + 2 * t;
            int k1 = k0 + 8;
            uint32_t h0, l0, h1, l1;
            split2(W[k0 * 128 + n], W[(k0 + 1) * 128 + n], h0, l0);
            split2(W[k1 * 128 + n], W[(k1 + 1) * 128 + n], h1, l1);
            uint4 v; v.x = h0; v.y = h1; v.z = l0; v.w = l1;
            d_Wfrag[(L * 128 + kt * 16 + nt) * 32 + lane] = v;
        } else {
            int r = idx - 3 * 4096;
            int lane = r & 31;
            int nt = (r >> 5) & 3;
            int kt = (r >> 7) & 7;
            int g = lane >> 2, t = lane & 3;
            int n = nt * 8 + g;
            int k0 = kt * 16 + 2 * t;
            int k1 = k0 + 8;
            uint32_t h0, l0, h1, l1;
            split2(Wf1[k0 * 32 + n], Wf1[(k0 + 1) * 32 + n], h0, l0);
            split2(Wf1[k1 * 32 + n], Wf1[(k1 + 1) * 32 + n], h1, l1);
            uint4 v; v.x = h0; v.y = h1; v.z = l0; v.w = l1;
            d_Wfrag[(384 + kt * 4 + nt) * 32 + lane] = v;
        }
    }
}

// count: 4 edges per thread via int4 (N_EDGES % 4 == 0)
__global__ void k_count(const int* __restrict__ ei) {
    int e4 = blockIdx.x * blockDim.x + threadIdx.x;
    if (e4 < N_EDGES / 4) {
        int4 d = __ldg(&((const int4*)(ei + N_EDGES))[e4]);
        atomicAdd(&d_cnt[d.x], 1);
        atomicAdd(&d_cnt[d.y], 1);
        atomicAdd(&d_cnt[d.z], 1);
        atomicAdd(&d_cnt[d.w], 1);
    }
}
__global__ void k_scan_local() {
    __shared__ int s[1024];
    int tid = threadIdx.x;
    int idx = blockIdx.x * 1024 + tid;
    int v = (idx < N_NODES) ? d_cnt[idx] : 0;
    if (idx < N_NODES) d_dinv[idx] = rsqrtf((float)v + 1.0f);   // fused dinv
    s[tid] = v;
    __syncthreads();
    for (int off = 1; off < 1024; off <<= 1) {
        int t = (tid >= off) ? s[tid - off] : 0;
        __syncthreads();
        s[tid] += t;
        __syncthreads();
    }
    if (idx < N_NODES) d_rowptr[idx] = s[tid] - v;   // exclusive
    if (tid == 1023) d_bsums[blockIdx.x] = s[1023];
}
// scan_add with inlined bsums prefix (every block recomputes the 128-wide scan)
__global__ void k_scan_add(int nb) {
    __shared__ int sb[128];
    int t = threadIdx.x;
    if (t < 128) sb[t] = (t < nb) ? d_bsums[t] : 0;
    __syncthreads();
    #pragma unroll
    for (int off = 1; off < 128; off <<= 1) {
        int v = (t < 128 && t >= off) ? sb[t - off] : 0;
        __syncthreads();
        if (t < 128) sb[t] += v;
        __syncthreads();
    }
    int idx = blockIdx.x * 1024 + t;
    int off = (blockIdx.x > 0) ? sb[blockIdx.x - 1] : 0;
    if (idx < N_NODES) d_rowptr[idx] += off;
    if (blockIdx.x == 0 && t == 0) d_rowptr[N_NODES] = sb[nb - 1];
}
// fill: 4 edges per thread via int4
__global__ void k_fill(const int* __restrict__ ei) {
    int e4 = blockIdx.x * blockDim.x + threadIdx.x;
    if (e4 < N_EDGES / 4) {
        int4 s = __ldg(&((const int4*)ei)[e4]);
        int4 d = __ldg(&((const int4*)(ei + N_EDGES))[e4]);
        int p;
        p = d_rowptr[d.x] + atomicAdd(&d_cursor[d.x], 1); d_col[p] = s.x;
        p = d_rowptr[d.y] + atomicAdd(&d_cursor[d.y], 1); d_col[p] = s.y;
        p = d_rowptr[d.z] + atomicAdd(&d_cursor[d.z], 1); d_col[p] = s.z;
        p = d_rowptr[d.w] + atomicAdd(&d_cursor[d.w], 1); d_col[p] = s.w;
    }
}

// ---------------- tensor GEMM: d_g(fp16) = dinv * (h_new @ W_layer) ----------------
// first=1: h_new = relu(x@We+be) (encoder); also zeroes all 4 BN stat buffers (CTA 0).
// first=0: h_new = relu(bnA*agg + bnC) + h_old, coeffs computed inline from buf bn_rd.
__global__ void __launch_bounds__(256, 2) k_mma_gemm(
    const float* __restrict__ x, const float* __restrict__ We,
    const float* __restrict__ be,
    const float* __restrict__ gamma, const float* __restrict__ beta,
    int layer, int hin_sel, int hout_sel, int first, int bn_rd) {
    extern __shared__ float smf[];
    const int lane = threadIdx.x & 31;
    const int wid = threadIdx.x >> 5;
    const int tile = blockIdx.x;
    float* sw = smf + wid * 16 * SM_STRIDE;
    const int rbase = tile * 128 + wid * 16;

    if (first && blockIdx.x == 0 && threadIdx.x < HID) {
        #pragma unroll
        for (int r = 0; r < 4; r++) {
            d_bnSum[r][threadIdx.x] = 0.0;
            d_bnSqs[r][threadIdx.x] = 0.0;
        }
    }

    // ---- phase 1: h_new for this warp's 16 rows ----
    if (first) {
        float4 w0 = __ldg(&((const float4*)We)[lane]);
        float4 w1 = __ldg(&((const float4*)We)[32 + lane]);
        float4 b  = __ldg(&((const float4*)be)[lane]);
        float4* H04 = reinterpret_cast<float4*>(d_h0);
        #pragma unroll 4
        for (int r = 0; r < 16; r++) {
            int row = rbase + r;
            int rs = (row < N_NODES) ? row : N_NODES - 1;
            float x0 = __ldg(&x[2 * rs]), x1 = __ldg(&x[2 * rs + 1]);
            float4 h;
            h.x = fmaxf(fmaf(x0, w0.x, fmaf(x1, w1.x, b.x)), 0.f);
            h.y = fmaxf(fmaf(x0, w0.y, fmaf(x1, w1.y, b.y)), 0.f);
            h.z = fmaxf(fmaf(x0, w0.z, fmaf(x1, w1.z, b.z)), 0.f);
            h.w = fmaxf(fmaf(x0, w0.w, fmaf(x1, w1.w, b.w)), 0.f);
            if (row < N_NODES) H04[(size_t)row * 32 + lane] = h;
            *reinterpret_cast<float4*>(sw + r * SM_STRIDE + 4 * lane) = h;
        }
    } else {
        float4 ba, bc;
        bn_coeffs4(bn_rd, lane, gamma, beta, ba, bc);
        const float4* A4 = reinterpret_cast<const float4*>(d_agg);
        const float4* HI4 = reinterpret_cast<const float4*>(hbuf(hin_sel));
        float4* HO4 = reinterpret_cast<float4*>(hbuf(hout_sel));
        #pragma unroll 4
        for (int r = 0; r < 16; r++) {
            int row = rbase + r;
            int rs = (row < N_NODES) ? row : N_NODES - 1;
            float4 v = A4[(size_t)rs * 32 + lane];
            float4 ho = HI4[(size_t)rs * 32 + lane];
            float4 h;
            h.x = fmaxf(fmaf(ba.x, v.x, bc.x), 0.f) + ho.x;
            h.y = fmaxf(fmaf(ba.y, v.y, bc.y), 0.f) + ho.y;
            h.z = fmaxf(fmaf(ba.z, v.z, bc.z), 0.f) + ho.z;
            h.w = fmaxf(fmaf(ba.w, v.w, bc.w), 0.f) + ho.w;
            if (row < N_NODES) HO4[(size_t)row * 32 + lane] = h;
            *reinterpret_cast<float4*>(sw + r * SM_STRIDE + 4 * lane) = h;
        }
    }
    __syncwarp();

    // ---- phase 2: A fragments (split bf16), 8 k-tiles ----
    const int g = lane >> 2, t = lane & 3;
    const float* r0p = sw + g * SM_STRIDE;
    const float* r1p = sw + (g + 8) * SM_STRIDE;
    uint32_t ah[32], al[32];
    #pragma unroll
    for (int kt = 0; kt < 8; kt++) {
        float2 p0 = *reinterpret_cast<const float2*>(r0p + 16 * kt + 2 * t);
        float2 p1 = *reinterpret_cast<const float2*>(r1p + 16 * kt + 2 * t);
        float2 p2 = *reinterpret_cast<const float2*>(r0p + 16 * kt + 2 * t + 8);
        float2 p3 = *reinterpret_cast<const float2*>(r1p + 16 * kt + 2 * t + 8);
        split2(p0.x, p0.y, ah[4 * kt + 0], al[4 * kt + 0]);
        split2(p1.x, p1.y, ah[4 * kt + 1], al[4 * kt + 1]);
        split2(p2.x, p2.y, ah[4 * kt + 2], al[4 * kt + 2]);
        split2(p3.x, p3.y, ah[4 * kt + 3], al[4 * kt + 3]);
    }

    // ---- phase 3: mma over 16 n-tiles (2 at a time), 3-pass split bf16; fp16 epilogue ----
    const uint4* Wf = &d_Wfrag[layer * 128 * 32];
    int row0 = rbase + g, row1 = rbase + g + 8;
    float dv0 = d_dinv[(row0 < N_NODES) ? row0 : 0];
    float dv1 = d_dinv[(row1 < N_NODES) ? row1 : 0];

    #pragma unroll
    for (int ntp = 0; ntp < 8; ntp++) {
        float c0[4] = {0.f, 0.f, 0.f, 0.f};
        float c1[4] = {0.f, 0.f, 0.f, 0.f};
        #pragma unroll
        for (int kt = 0; kt < 8; kt++) {
            uint4 B0 = __ldg(&Wf[(kt * 16 + 2 * ntp) * 32 + lane]);
            uint4 B1 = __ldg(&Wf[(kt * 16 + 2 * ntp + 1) * 32 + lane]);
            uint32_t a0 = ah[4 * kt], a1 = ah[4 * kt + 1], a2 = ah[4 * kt + 2], a3 = ah[4 * kt + 3];
            uint32_t l0 = al[4 * kt], l1 = al[4 * kt + 1], l2 = al[4 * kt + 2], l3 = al[4 * kt + 3];
            mma_bf16(c0, a0, a1, a2, a3, B0.x, B0.y);   // Ah * Bh
            mma_bf16(c0, l0, l1, l2, l3, B0.x, B0.y);   // Al * Bh
            mma_bf16(c0, a0, a1, a2, a3, B0.z, B0.w);   // Ah * Bl
            mma_bf16(c1, a0, a1, a2, a3, B1.x, B1.y);
            mma_bf16(c1, l0, l1, l2, l3, B1.x, B1.y);
            mma_bf16(c1, a0, a1, a2, a3, B1.z, B1.w);
        }
        int col0 = (2 * ntp) * 8 + 2 * t;
        int col1 = (2 * ntp + 1) * 8 + 2 * t;
        if (row0 < N_NODES) {
            *reinterpret_cast<__half2*>(d_g + (size_t)row0 * 128 + col0) =
                __floats2half2_rn(c0[0] * dv0, c0[1] * dv0);
            *reinterpret_cast<__half2*>(d_g + (size_t)row0 * 128 + col1) =
                __floats2half2_rn(c1[0] * dv0, c1[1] * dv0);
        }
        if (row1 < N_NODES) {
            *reinterpret_cast<__half2*>(d_g + (size_t)row1 * 128 + col0) =
                __floats2half2_rn(c0[2] * dv1, c0[3] * dv1);
            *reinterpret_cast<__half2*>(d_g + (size_t)row1 * 128 + col1) =
                __floats2half2_rn(c1[2] * dv1, c1[3] * dv1);
        }
    }
}

// ---------------- aggregation: agg[i] = dinv[i]*(sum_in g[src] + g[i]); BN partials ---
// 2 nodes per warp iteration, each unrolled x4 -> up to 8 gathers in flight
__global__ void k_aggregate(int bw) {
    __shared__ float sS[HID];
    __shared__ float sQ[HID];
    if (threadIdx.x < HID) { sS[threadIdx.x] = 0.f; sQ[threadIdx.x] = 0.f; }
    __syncthreads();

    const int lane = threadIdx.x & 31;
    const int gwid = (blockIdx.x * blockDim.x + threadIdx.x) >> 5;
    const int nwarps = (gridDim.x * blockDim.x) >> 5;
    const uint2* g2 = reinterpret_cast<const uint2*>(d_g);
    float4* agg4 = reinterpret_cast<float4*>(d_agg);

    float4 lsum = make_float4(0.f, 0.f, 0.f, 0.f);
    float4 lsq  = make_float4(0.f, 0.f, 0.f, 0.f);

    for (int i = gwid * 2; i < N_NODES; i += nwarps * 2) {
        int j = i + 1;
        bool hasj = (j < N_NODES);
        float4 accA = make_float4(0.f, 0.f, 0.f, 0.f);
        float4 accB = make_float4(0.f, 0.f, 0.f, 0.f);
        addh4(accA, __ldg(&g2[(size_t)i * 32 + lane]));          // self loop A
        if (hasj) addh4(accB, __ldg(&g2[(size_t)j * 32 + lane]));// self loop B
        int eA = d_rowptr[i],  eA1 = d_rowptr[i + 1];
        int eB = hasj ? eA1 : 0, eB1 = hasj ? d_rowptr[j + 1] : 0;

        // interleaved phase: both nodes have >=4 edges remaining
        while (eA + 4 <= eA1 && eB + 4 <= eB1) {
            int a0 = __ldg(&d_col[eA]),     a1 = __ldg(&d_col[eA + 1]);
            int a2 = __ldg(&d_col[eA + 2]), a3 = __ldg(&d_col[eA + 3]);
            int b0 = __ldg(&d_col[eB]),     b1 = __ldg(&d_col[eB + 1]);
            int b2 = __ldg(&d_col[eB + 2]), b3 = __ldg(&d_col[eB + 3]);
            uint2 vA0 = __ldg(&g2[(size_t)a0 * 32 + lane]);
            uint2 vA1 = __ldg(&g2[(size_t)a1 * 32 + lane]);
            uint2 vA2 = __ldg(&g2[(size_t)a2 * 32 + lane]);
            uint2 vA3 = __ldg(&g2[(size_t)a3 * 32 + lane]);
            uint2 vB0 = __ldg(&g2[(size_t)b0 * 32 + lane]);
            uint2 vB1 = __ldg(&g2[(size_t)b1 * 32 + lane]);
            uint2 vB2 = __ldg(&g2[(size_t)b2 * 32 + lane]);
            uint2 vB3 = __ldg(&g2[(size_t)b3 * 32 + lane]);
            addh4(accA, vA0); addh4(accA, vA1); addh4(accA, vA2); addh4(accA, vA3);
            addh4(accB, vB0); addh4(accB, vB1); addh4(accB, vB2); addh4(accB, vB3);
            eA += 4; eB += 4;
        }
        // tails (node A)
        for (; eA + 4 <= eA1; eA += 4) {
            int a0 = __ldg(&d_col[eA]),     a1 = __ldg(&d_col[eA + 1]);
            int a2 = __ldg(&d_col[eA + 2]), a3 = __ldg(&d_col[eA + 3]);
            uint2 v0 = __ldg(&g2[(size_t)a0 * 32 + lane]);
            uint2 v1 = __ldg(&g2[(size_t)a1 * 32 + lane]);
            uint2 v2 = __ldg(&g2[(size_t)a2 * 32 + lane]);
            uint2 v3 = __ldg(&g2[(size_t)a3 * 32 + lane]);
            addh4(accA, v0); addh4(accA, v1); addh4(accA, v2); addh4(accA, v3);
        }
        for (; eA < eA1; eA++) {
            int s0 = __ldg(&d_col[eA]);
            addh4(accA, __ldg(&g2[(size_t)s0 * 32 + lane]));
        }
        // tails (node B)
        for (; eB + 4 <= eB1; eB += 4) {
            int b0 = __ldg(&d_col[eB]),     b1 = __ldg(&d_col[eB + 1]);
            int b2 = __ldg(&d_col[eB + 2]), b3 = __ldg(&d_col[eB + 3]);
            uint2 v0 = __ldg(&g2[(size_t)b0 * 32 + lane]);
            uint2 v1 = __ldg(&g2[(size_t)b1 * 32 + lane]);
            uint2 v2 = __ldg(&g2[(size_t)b2 * 32 + lane]);
            uint2 v3 = __ldg(&g2[(size_t)b3 * 32 + lane]);
            addh4(accB, v0); addh4(accB, v1); addh4(accB, v2); addh4(accB, v3);
        }
        for (; eB < eB1; eB++) {
            int s0 = __ldg(&d_col[eB]);
            addh4(accB, __ldg(&g2[(size_t)s0 * 32 + lane]));
        }

        float dvA = d_dinv[i];
        accA.x *= dvA; accA.y *= dvA; accA.z *= dvA; accA.w *= dvA;
        __stcs(&agg4[(size_t)i * 32 + lane], accA);
        lsum.x += accA.x; lsum.y += accA.y; lsum.z += accA.z; lsum.w += accA.w;
        lsq.x = fmaf(accA.x, accA.x, lsq.x);
        lsq.y = fmaf(accA.y, accA.y, lsq.y);
        lsq.z = fmaf(accA.z, accA.z, lsq.z);
        lsq.w = fmaf(accA.w, accA.w, lsq.w);
        if (hasj) {
            float dvB = d_dinv[j];
            accB.x *= dvB; accB.y *= dvB; accB.z *= dvB; accB.w *= dvB;
            __stcs(&agg4[(size_t)j * 32 + lane], accB);
            lsum.x += accB.x; lsum.y += accB.y; lsum.z += accB.z; lsum.w += accB.w;
            lsq.x = fmaf(accB.x, accB.x, lsq.x);
            lsq.y = fmaf(accB.y, accB.y, lsq.y);
            lsq.z = fmaf(accB.z, accB.z, lsq.z);
            lsq.w = fmaf(accB.w, accB.w, lsq.w);
        }
    }
    int f = 4 * lane;
    atomicAdd(&sS[f + 0], lsum.x); atomicAdd(&sS[f + 1], lsum.y);
    atomicAdd(&sS[f + 2], lsum.z); atomicAdd(&sS[f + 3], lsum.w);
    atomicAdd(&sQ[f + 0], lsq.x);  atomicAdd(&sQ[f + 1], lsq.y);
    atomicAdd(&sQ[f + 2], lsq.z);  atomicAdd(&sQ[f + 3], lsq.w);
    __syncthreads();
    if (threadIdx.x < HID) {
        atomicAdd(&d_bnSum[bw][threadIdx.x], (double)sS[threadIdx.x]);
        atomicAdd(&d_bnSqs[bw][threadIdx.x], (double)sQ[threadIdx.x]);
    }
}

// ---------------- head: h3 = BN3(agg)+h2 (smem only); ff = h3@Wf1 via mma; stats->buf3 --
__global__ void __launch_bounds__(256, 2) k_mma_head(
    const float* __restrict__ gamma, const float* __restrict__ beta,
    int hin_sel, int bn_rd) {
    extern __shared__ float smf[];
    __shared__ float sS[32];
    __shared__ float sQ[32];
    const int lane = threadIdx.x & 31;
    const int wid = threadIdx.x >> 5;
    const int tile = blockIdx.x;
    float* sw = smf + wid * 16 * SM_STRIDE;
    const int rbase = tile * 128 + wid * 16;

    if (threadIdx.x < 32) { sS[threadIdx.x] = 0.f; sQ[threadIdx.x] = 0.f; }
    __syncthreads();

    // ---- phase 1: h3 rows into smem (no gmem store) ----
    {
        float4 ba, bc;
        bn_coeffs4(bn_rd, lane, gamma, beta, ba, bc);
        const float4* A4 = reinterpret_cast<const float4*>(d_agg);
        const float4* HI4 = reinterpret_cast<const float4*>(hbuf(hin_sel));
        #pragma unroll 4
        for (int r = 0; r < 16; r++) {
            int row = rbase + r;
            int rs = (row < N_NODES) ? row : N_NODES - 1;
            float4 v = A4[(size_t)rs * 32 + lane];
            float4 ho = HI4[(size_t)rs * 32 + lane];
            float4 h;
            h.x = fmaxf(fmaf(ba.x, v.x, bc.x), 0.f) + ho.x;
            h.y = fmaxf(fmaf(ba.y, v.y, bc.y), 0.f) + ho.y;
            h.z = fmaxf(fmaf(ba.z, v.z, bc.z), 0.f) + ho.z;
            h.w = fmaxf(fmaf(ba.w, v.w, bc.w), 0.f) + ho.w;
            *reinterpret_cast<float4*>(sw + r * SM_STRIDE + 4 * lane) = h;
        }
    }
    __syncwarp();

    // ---- phase 2: A fragments ----
    const int g = lane >> 2, t = lane & 3;
    const float* r0p = sw + g * SM_STRIDE;
    const float* r1p = sw + (g + 8) * SM_STRIDE;
    uint32_t ah[32], al[32];
    #pragma unroll
    for (int kt = 0; kt < 8; kt++) {
        float2 p0 = *reinterpret_cast<const float2*>(r0p + 16 * kt + 2 * t);
        float2 p1 = *reinterpret_cast<const float2*>(r1p + 16 * kt + 2 * t);
        float2 p2 = *reinterpret_cast<const float2*>(r0p + 16 * kt + 2 * t + 8);
        float2 p3 = *reinterpret_cast<const float2*>(r1p + 16 * kt + 2 * t + 8);
        split2(p0.x, p0.y, ah[4 * kt + 0], al[4 * kt + 0]);
        split2(p1.x, p1.y, ah[4 * kt + 1], al[4 * kt + 1]);
        split2(p2.x, p2.y, ah[4 * kt + 2], al[4 * kt + 2]);
        split2(p3.x, p3.y, ah[4 * kt + 3], al[4 * kt + 3]);
    }

    // ---- phase 3: N=32 -> 2 ntp iterations; ff fp32 into d_g bytes; local stats ----
    const uint4* Wf = &d_Wfrag[384 * 32];
    float* ff = reinterpret_cast<float*>(d_g);
    int row0 = rbase + g, row1 = rbase + g + 8;
    bool v0 = row0 < N_NODES, v1 = row1 < N_NODES;
    float sl[8] = {0, 0, 0, 0, 0, 0, 0, 0};
    float ql[8] = {0, 0, 0, 0, 0, 0, 0, 0};

    #pragma unroll
    for (int ntp = 0; ntp < 2; ntp++) {
        float c0[4] = {0.f, 0.f, 0.f, 0.f};
        float c1[4] = {0.f, 0.f, 0.f, 0.f};
        #pragma unroll
        for (int kt = 0; kt < 8; kt++) {
            uint4 B0 = __ldg(&Wf[(kt * 4 + 2 * ntp) * 32 + lane]);
            uint4 B1 = __ldg(&Wf[(kt * 4 + 2 * ntp + 1) * 32 + lane]);
            uint32_t a0 = ah[4 * kt], a1 = ah[4 * kt + 1], a2 = ah[4 * kt + 2], a3 = ah[4 * kt + 3];
            uint32_t l0 = al[4 * kt], l1 = al[4 * kt + 1], l2 = al[4 * kt + 2], l3 = al[4 * kt + 3];
            mma_bf16(c0, a0, a1, a2, a3, B0.x, B0.y);
            mma_bf16(c0, l0, l1, l2, l3, B0.x, B0.y);
            mma_bf16(c0, a0, a1, a2, a3, B0.z, B0.w);
            mma_bf16(c1, a0, a1, a2, a3, B1.x, B1.y);
            mma_bf16(c1, l0, l1, l2, l3, B1.x, B1.y);
            mma_bf16(c1, a0, a1, a2, a3, B1.z, B1.w);
        }
        int col0 = (2 * ntp) * 8 + 2 * t;
        int col1 = col0 + 8;
        if (v0) {
            *reinterpret_cast<float2*>(ff + (size_t)row0 * 32 + col0) = make_float2(c0[0], c0[1]);
            *reinterpret_cast<float2*>(ff + (size_t)row0 * 32 + col1) = make_float2(c1[0], c1[1]);
            sl[4 * ntp + 0] += c0[0]; ql[4 * ntp + 0] += c0[0] * c0[0];
            sl[4 * ntp + 1] += c0[1]; ql[4 * ntp + 1] += c0[1] * c0[1];
            sl[4 * ntp + 2] += c1[0]; ql[4 * ntp + 2] += c1[0] * c1[0];
            sl[4 * ntp + 3] += c1[1]; ql[4 * ntp + 3] += c1[1] * c1[1];
        }
        if (v1) {
            *reinterpret_cast<float2*>(ff + (size_t)row1 * 32 + col0) = make_float2(c0[2], c0[3]);
            *reinterpret_cast<float2*>(ff + (size_t)row1 * 32 + col1) = make_float2(c1[2], c1[3]);
            sl[4 * ntp + 0] += c0[2]; ql[4 * ntp + 0] += c0[2] * c0[2];
            sl[4 * ntp + 1] += c0[3]; ql[4 * ntp + 1] += c0[3] * c0[3];
            sl[4 * ntp + 2] += c1[2]; ql[4 * ntp + 2] += c1[2] * c1[2];
            sl[4 * ntp + 3] += c1[3]; ql[4 * ntp + 3] += c1[3] * c1[3];
        }
    }

    // reduce over g (lanes xor 4,8,16), then lanes 0..3 (t==lane) hold totals
    #pragma unroll
    for (int off = 4; off < 32; off <<= 1) {
        #pragma unroll
        for (int j = 0; j < 8; j++) {
            sl[j] += __shfl_xor_sync(0xffffffffu, sl[j], off);
            ql[j] += __shfl_xor_sync(0xffffffffu, ql[j], off);
        }
    }
    if (lane < 4) {
        #pragma unroll
        for (int j = 0; j < 8; j++) {
            // j = 4*ntp + k : feature = 16*ntp + 8*(k>>1) + 2*lane + (k&1)
            int ntp = j >> 2, k = j & 3;
            int feat = 16 * ntp + 8 * (k >> 1) + 2 * lane + (k & 1);
            atomicAdd(&sS[feat], sl[j]);
            atomicAdd(&sQ[feat], ql[j]);
        }
    }
    __syncthreads();
    if (threadIdx.x < 32) {
        atomicAdd(&d_bnSum[3][threadIdx.x], (double)sS[threadIdx.x]);
        atomicAdd(&d_bnSqs[3][threadIdx.x], (double)sQ[threadIdx.x]);
    }
}

// ---------------- out = tanh(relu(a*ff+c) @ Wf2 + bf2), BN coeffs inline from buf3 ------
__global__ void k_out(const float* __restrict__ gf, const float* __restrict__ btf,
                      const float* __restrict__ Wf2,
                      const float* __restrict__ bf2,
                      float* __restrict__ out) {
    __shared__ float sA[32], sC[32], sW[64], sB[2];
    int t = threadIdx.x;
    if (t < 32) {
        const float invn = 1.0f / (float)N_NODES;
        float m = (float)d_bnSum[3][t] * invn;
        float v = (float)d_bnSqs[3][t] * invn - m * m;
        float a = __ldg(&gf[t]) * rsqrtf(v + EPS);
        sA[t] = a;
        sC[t] = __ldg(&btf[t]) - m * a;
    }
    if (t < 64) sW[t] = Wf2[t];
    if (t < 2) sB[t] = bf2[t];
    __syncthreads();
    int i = blockIdx.x * blockDim.x + t;
    if (i >= N_NODES) return;
    float a0 = sB[0], a1 = sB[1];
    const float4* f4 = reinterpret_cast<const float4*>(reinterpret_cast<const float*>(d_g) + (size_t)i * 32);
    #pragma unroll
    for (int j4 = 0; j4 < 8; j4++) {
        float4 v = f4[j4];
        int j = j4 * 4;
        float f;
        f = fmaxf(fmaf(sA[j + 0], v.x, sC[j + 0]), 0.f); a0 = fmaf(f, sW[2 * (j + 0)], a0); a1 = fmaf(f, sW[2 * (j + 0) + 1], a1);
        f = fmaxf(fmaf(sA[j + 1], v.y, sC[j + 1]), 0.f); a0 = fmaf(f, sW[2 * (j + 1)], a0); a1 = fmaf(f, sW[2 * (j + 1) + 1], a1);
        f = fmaxf(fmaf(sA[j + 2], v.z, sC[j + 2]), 0.f); a0 = fmaf(f, sW[2 * (j + 2)], a0); a1 = fmaf(f, sW[2 * (j + 2) + 1], a1);
        f = fmaxf(fmaf(sA[j + 3], v.w, sC[j + 3]), 0.f); a0 = fmaf(f, sW[2 * (j + 3)], a0); a1 = fmaf(f, sW[2 * (j + 3) + 1], a1);
    }
    out[2 * i]     = tanhf(a0);
    out[2 * i + 1] = tanhf(a1);
}

// ---------------- launch ----------------
extern "C" void kernel_launch(void* const* d_in, const int* in_sizes, int n_in,
                              void* d_out, int out_size) {
    const float* x    = (const float*)d_in[0];
    const int*   ei   = (const int*)d_in[1];
    const float* We   = (const float*)d_in[2];
    const float* be   = (const float*)d_in[3];
    const float* W1   = (const float*)d_in[4];
    const float* g1   = (const float*)d_in[6];
    const float* bt1  = (const float*)d_in[7];
    const float* W2   = (const float*)d_in[8];
    const float* g2   = (const float*)d_in[10];
    const float* bt2  = (const float*)d_in[11];
    const float* W3   = (const float*)d_in[12];
    const float* g3   = (const float*)d_in[14];
    const float* bt3  = (const float*)d_in[15];
    const float* Wf1  = (const float*)d_in[16];
    const float* gf   = (const float*)d_in[18];
    const float* btf  = (const float*)d_in[19];
    const float* Wf2  = (const float*)d_in[20];
    const float* bf2  = (const float*)d_in[21];
    float* out = (float*)d_out;
    // (b1/b2/b3/bf1 unused: uniform per-feature bias cancels inside BatchNorm)

    cudaFuncSetAttribute(k_mma_gemm, cudaFuncAttributeMaxDynamicSharedMemorySize, SMEM_MMA);
    cudaFuncSetAttribute(k_mma_head, cudaFuncAttributeMaxDynamicSharedMemorySize, SMEM_MMA);

    const int nb_scan = (N_NODES + 1023) / 1024;   // 98
    const int GB = 592;

    // graph preprocessing: zero+wfrag fused; count/fill vectorized; scan (dinv fused)
    k_pre0<<<NB_ZERO + NB_WFRAG, 256>>>(W1, W2, W3, Wf1);
    k_count<<<(N_EDGES / 4 + 255) / 256, 256>>>(ei);
    k_scan_local<<<nb_scan, 1024>>>();
    k_scan_add<<<nb_scan, 1024>>>(nb_scan);
    k_fill<<<(N_EDGES / 4 + 255) / 256, 256>>>(ei);

    // block 1: encoder fused; zeroes all BN bufs; h0 -> g ; stats -> buf0
    k_mma_gemm<<<N_TILES, 256, SMEM_MMA>>>(x, We, be, nullptr, nullptr, 0, 0, 0, 1, 0);
    k_aggregate<<<GB, 256>>>(0);

    // block 2: BN1 (buf0) fused; h0 -> h1 -> g ; stats -> buf1
    k_mma_gemm<<<N_TILES, 256, SMEM_MMA>>>(nullptr, nullptr, nullptr, g1, bt1, 1, 0, 1, 0, 0);
    k_aggregate<<<GB, 256>>>(1);

    // block 3: BN2 (buf1) fused; h1 -> h0 -> g ; stats -> buf2
    k_mma_gemm<<<N_TILES, 256, SMEM_MMA>>>(nullptr, nullptr, nullptr, g2, bt2, 2, 1, 0, 0, 1);
    k_aggregate<<<GB, 256>>>(2);

    // head: BN3 (buf2) fused; h2 in d_h0 -> ff (fp32 in d_g bytes) + stats -> buf3
    k_mma_head<<<N_TILES, 256, SMEM_MMA>>>(g3, bt3, 0, 2);
    k_out<<<(N_NODES + 127) / 128, 128>>>(gf, btf, Wf2, bf2, out);

    (void)in_sizes; (void)n_in; (void)out_size;
}